// round 7
// baseline (speedup 1.0000x reference)
#include <cuda_runtime.h>
#include <cuda_bf16.h>
#include <math.h>

// ---------------------------------------------------------------------------
// MambaSSD: out = ((C*h + D*xi) * silu(z)) @ W_out
//   xz = x@W_in -> xi,z ; proj = xi@W_xp -> delta,B_raw,C_raw
//   B = B_raw@W_B ; C = C_raw@W_C ; a_t = exp(-exp(A_log)*softplus(delta))
//   h_t = a_t*h_{t-1} + B_t*xi_t  (seq scan; a is channel-independent)
//
// Round 5: fp32 SIMT pipeline, hardened capture path: NO host API calls in
// kernel_launch except the 7 kernel launches. All scratch referenced as
// __device__ globals directly from device code.
// ---------------------------------------------------------------------------

#define BATCH 4
#define SEQ   2048
#define DM    1024
#define DI    2048
#define DS    64
#define MTOK  (BATCH * SEQ)   // 8192 tokens
#define NCH   16
#define CHUNK 128             // SEQ / NCH

// ------------------------- scratch (device globals) ------------------------
__device__ float g_xi[MTOK * DI];        // 64 MB
__device__ float g_sz[MTOK * DI];        // silu(z), 64 MB
__device__ float g_a[MTOK];              // per-token decay
__device__ float g_Braw[MTOK * DS];
__device__ float g_Craw[MTOK * DS];
__device__ float g_B[MTOK * DI];         // 64 MB
__device__ float g_C[MTOK * DI];         // 64 MB
__device__ float g_y[MTOK * DI];         // 64 MB
__device__ float g_Hend[BATCH * NCH * DI];
__device__ float g_Hcarry[BATCH * NCH * DI];
__device__ float g_Aprod[BATCH * NCH];

// ------------------------------ SGEMM 128x128x8 ----------------------------
// C[M,N] = A[M,K] @ B[K,N], row-major. 256 threads, 8x8 per thread.
// EPI 0: plain store to C0.
// EPI 1: xz split epilogue: cols [0,DI) -> g_xi, cols [DI,2DI) -> g_sz=silu(z).
#define BM 128
#define BN 128
#define BKK 8

template<int EPI>
__device__ __forceinline__
void sgemm_dev(const float* __restrict__ A, const float* __restrict__ B,
               float* __restrict__ C0, int N, int K)
{
    __shared__ float As[BKK][BM];
    __shared__ float Bs[BKK][BN];

    const int tid = threadIdx.x;
    const int rowBase = blockIdx.y * BM;
    const int colBase = blockIdx.x * BN;

    const int aRow = tid >> 1;          // 0..127
    const int aK   = (tid & 1) * 4;     // 0 or 4
    const int bK   = tid >> 5;          // 0..7
    const int bCol = (tid & 31) * 4;

    const float* Aptr = A + (size_t)(rowBase + aRow) * K + aK;
    const float* Bptr = B + (size_t)bK * N + colBase + bCol;

    const int ty = tid >> 4;            // 0..15 -> row group
    const int tx = tid & 15;            // 0..15 -> col group

    float acc[8][8];
#pragma unroll
    for (int i = 0; i < 8; i++)
#pragma unroll
        for (int j = 0; j < 8; j++) acc[i][j] = 0.f;

    for (int k0 = 0; k0 < K; k0 += BKK) {
        float4 av = *(const float4*)(Aptr + k0);
        float4 bv = *(const float4*)(Bptr + (size_t)k0 * N);
        __syncthreads();
        As[aK + 0][aRow] = av.x;
        As[aK + 1][aRow] = av.y;
        As[aK + 2][aRow] = av.z;
        As[aK + 3][aRow] = av.w;
        *(float4*)&Bs[bK][bCol] = bv;
        __syncthreads();

#pragma unroll
        for (int kk = 0; kk < BKK; kk++) {
            float4 a0 = *(const float4*)(&As[kk][ty * 8]);
            float4 a1 = *(const float4*)(&As[kk][ty * 8 + 4]);
            float4 b0 = *(const float4*)(&Bs[kk][tx * 8]);
            float4 b1 = *(const float4*)(&Bs[kk][tx * 8 + 4]);
            float ar[8] = {a0.x, a0.y, a0.z, a0.w, a1.x, a1.y, a1.z, a1.w};
            float br[8] = {b0.x, b0.y, b0.z, b0.w, b1.x, b1.y, b1.z, b1.w};
#pragma unroll
            for (int i = 0; i < 8; i++)
#pragma unroll
                for (int j = 0; j < 8; j++)
                    acc[i][j] = fmaf(ar[i], br[j], acc[i][j]);
        }
    }

    if (EPI == 0) {
#pragma unroll
        for (int i = 0; i < 8; i++) {
            int row = rowBase + ty * 8 + i;
            float* cp = C0 + (size_t)row * N + colBase + tx * 8;
            *(float4*)cp       = make_float4(acc[i][0], acc[i][1], acc[i][2], acc[i][3]);
            *(float4*)(cp + 4) = make_float4(acc[i][4], acc[i][5], acc[i][6], acc[i][7]);
        }
    } else {
        // xz split: whole block is on one side since BN | DI
        bool zside = (colBase >= DI);
        int cb = zside ? (colBase - DI) : colBase;
#pragma unroll
        for (int i = 0; i < 8; i++) {
            int row = rowBase + ty * 8 + i;
            if (!zside) {
                float* cp = g_xi + (size_t)row * DI + cb + tx * 8;
                *(float4*)cp       = make_float4(acc[i][0], acc[i][1], acc[i][2], acc[i][3]);
                *(float4*)(cp + 4) = make_float4(acc[i][4], acc[i][5], acc[i][6], acc[i][7]);
            } else {
                float* cp = g_sz + (size_t)row * DI + cb + tx * 8;
                float v[8];
#pragma unroll
                for (int j = 0; j < 8; j++) {
                    float z = acc[i][j];
                    v[j] = z / (1.f + expf(-z));   // silu
                }
                *(float4*)cp       = make_float4(v[0], v[1], v[2], v[3]);
                *(float4*)(cp + 4) = make_float4(v[4], v[5], v[6], v[7]);
            }
        }
    }
}

// Thin global wrappers bound to device-global scratch (no host symbol queries).
__global__ __launch_bounds__(256)
void k_gemm_in(const float* __restrict__ x, const float* __restrict__ W_in)
{
    sgemm_dev<1>(x, W_in, nullptr, 2 * DI, DM);
}

__global__ __launch_bounds__(256)
void k_gemm_bc(const float* __restrict__ W_B, const float* __restrict__ W_C)
{
    if (blockIdx.z == 0) sgemm_dev<0>(g_Braw, W_B, g_B, DI, DS);
    else                 sgemm_dev<0>(g_Craw, W_C, g_C, DI, DS);
}

__global__ __launch_bounds__(256)
void k_gemm_out(const float* __restrict__ W_out, float* __restrict__ out)
{
    sgemm_dev<0>(g_y, W_out, out, DM, DI);
}

// ------------------------- proj = xi @ W_xp (N=129) ------------------------
// Block: 160 threads (129 active, one output column each), 32 rows per block.
#define PRT 32
#define PKT 32
__global__ __launch_bounds__(160)
void proj_kernel(const float* __restrict__ Wxp, const float* __restrict__ A_log)
{
    __shared__ float xs[PKT][PRT + 4];   // [k][r]; row stride 144B (16B aligned)
    const int tid = threadIdx.x;
    const int row0 = blockIdx.x * PRT;
    const int col = tid;
    const bool active = (col < 129);

    float acc[PRT];
#pragma unroll
    for (int r = 0; r < PRT; r++) acc[r] = 0.f;

    for (int k0 = 0; k0 < DI; k0 += PKT) {
        __syncthreads();
        for (int i = tid; i < PRT * PKT; i += 160) {
            int r = i >> 5, c = i & 31;
            xs[c][r] = g_xi[(size_t)(row0 + r) * DI + k0 + c];
        }
        __syncthreads();

        float wv[PKT];
        if (active) {
#pragma unroll
            for (int kk = 0; kk < PKT; kk++)
                wv[kk] = Wxp[(size_t)(k0 + kk) * 129 + col];
        } else {
#pragma unroll
            for (int kk = 0; kk < PKT; kk++) wv[kk] = 0.f;
        }

#pragma unroll
        for (int kk = 0; kk < PKT; kk++) {
            float w = wv[kk];
#pragma unroll
            for (int r4 = 0; r4 < PRT / 4; r4++) {
                float4 xv = *(const float4*)(&xs[kk][r4 * 4]);
                acc[r4 * 4 + 0] = fmaf(xv.x, w, acc[r4 * 4 + 0]);
                acc[r4 * 4 + 1] = fmaf(xv.y, w, acc[r4 * 4 + 1]);
                acc[r4 * 4 + 2] = fmaf(xv.z, w, acc[r4 * 4 + 2]);
                acc[r4 * 4 + 3] = fmaf(xv.w, w, acc[r4 * 4 + 3]);
            }
        }
    }

    if (active) {
        float Aval = -expf(*A_log);
#pragma unroll 4
        for (int r = 0; r < PRT; r++) {
            int m = row0 + r;
            float v = acc[r];
            if (col == 0) {
                float dlt = (v > 20.f) ? v : log1pf(expf(v));  // softplus
                g_a[m] = expf(Aval * dlt);
            } else if (col <= DS) {
                g_Braw[(size_t)m * DS + (col - 1)] = v;
            } else {
                g_Craw[(size_t)m * DS + (col - 1 - DS)] = v;
            }
        }
    }
}

// ------------------------------- 3-phase scan ------------------------------
__global__ __launch_bounds__(256)
void scan_chunk_kernel()
{
    __shared__ float as_[CHUNK];
    const int d = blockIdx.x * blockDim.x + threadIdx.x;
    const int c = blockIdx.y, b = blockIdx.z;
    const int m0 = b * SEQ + c * CHUNK;
    if (threadIdx.x < CHUNK) as_[threadIdx.x] = g_a[m0 + threadIdx.x];
    __syncthreads();

    const float* bp = g_B  + (size_t)m0 * DI + d;
    const float* xp = g_xi + (size_t)m0 * DI + d;
    float h = 0.f;
#pragma unroll 4
    for (int t = 0; t < CHUNK; t++)
        h = fmaf(as_[t], h, bp[(size_t)t * DI] * xp[(size_t)t * DI]);

    g_Hend[((size_t)(b * NCH + c)) * DI + d] = h;
    if (blockIdx.x == 0 && threadIdx.x == 0) {
        float ap = 1.f;
#pragma unroll
        for (int t = 0; t < CHUNK; t++) ap *= as_[t];
        g_Aprod[b * NCH + c] = ap;
    }
}

__global__ __launch_bounds__(256)
void scan_carry_kernel()
{
    const int idx = blockIdx.x * blockDim.x + threadIdx.x;  // 0..8191
    const int b = idx / DI, d = idx % DI;
    float carry = 0.f;
#pragma unroll
    for (int c = 0; c < NCH; c++) {
        size_t o = ((size_t)(b * NCH + c)) * DI + d;
        g_Hcarry[o] = carry;
        carry = fmaf(g_Aprod[b * NCH + c], carry, g_Hend[o]);
    }
}

__global__ __launch_bounds__(256)
void scan_final_kernel(const float* __restrict__ Dvec)
{
    __shared__ float as_[CHUNK];
    const int d = blockIdx.x * blockDim.x + threadIdx.x;
    const int c = blockIdx.y, b = blockIdx.z;
    const int m0 = b * SEQ + c * CHUNK;
    if (threadIdx.x < CHUNK) as_[threadIdx.x] = g_a[m0 + threadIdx.x];
    __syncthreads();

    const float* bp  = g_B  + (size_t)m0 * DI + d;
    const float* xp  = g_xi + (size_t)m0 * DI + d;
    const float* cp  = g_C  + (size_t)m0 * DI + d;
    const float* szp = g_sz + (size_t)m0 * DI + d;
    float*       yp  = g_y  + (size_t)m0 * DI + d;

    const float Dd = Dvec[d];
    float h = g_Hcarry[((size_t)(b * NCH + c)) * DI + d];
#pragma unroll 4
    for (int t = 0; t < CHUNK; t++) {
        float xv = xp[(size_t)t * DI];
        h = fmaf(as_[t], h, bp[(size_t)t * DI] * xv);
        float yv = fmaf(cp[(size_t)t * DI], h, Dd * xv);
        yp[(size_t)t * DI] = yv * szp[(size_t)t * DI];
    }
}

// --------------------------------- launch ----------------------------------
extern "C" void kernel_launch(void* const* d_in, const int* in_sizes, int n_in,
                              void* d_out, int out_size)
{
    const float* x     = (const float*)d_in[0];
    const float* W_in  = (const float*)d_in[1];
    const float* W_xp  = (const float*)d_in[2];
    const float* W_B   = (const float*)d_in[3];
    const float* W_C   = (const float*)d_in[4];
    const float* W_out = (const float*)d_in[5];
    const float* Dvec  = (const float*)d_in[6];
    const float* A_log = (const float*)d_in[7];
    float* out = (float*)d_out;

    // 1) xz = x @ W_in  -> xi, silu(z)
    k_gemm_in<<<dim3((2 * DI) / BN, MTOK / BM), 256>>>(x, W_in);
    // 2) proj = xi @ W_xp -> a, B_raw, C_raw
    proj_kernel<<<MTOK / PRT, 160>>>(W_xp, A_log);
    // 3) B = B_raw @ W_B ; C = C_raw @ W_C   (one launch, z selects)
    k_gemm_bc<<<dim3(DI / BN, MTOK / BM, 2), 256>>>(W_B, W_C);
    // 4) chunked scan + gating -> y
    scan_chunk_kernel<<<dim3(DI / 256, NCH, BATCH), 256>>>();
    scan_carry_kernel<<<(BATCH * DI) / 256, 256>>>();
    scan_final_kernel<<<dim3(DI / 256, NCH, BATCH), 256>>>(Dvec);
    // 5) out = y @ W_out
    k_gemm_out<<<dim3(DM / BN, MTOK / BM), 256>>>(W_out, out);
}

// round 11
// speedup vs baseline: 2.5512x; 2.5512x over previous
#include <cuda_runtime.h>
#include <cuda_bf16.h>
#include <math.h>
#include <stdint.h>

// ---------------------------------------------------------------------------
// MambaSSD — mma.sync (bf16 split) GEMMs for x@W_in and y@W_out.
// tcgen05 is unavailable: harness builds PTX at target sm_103 (no 'a').
// out = ((C*h + D*xi) * silu(z)) @ W_out
// ---------------------------------------------------------------------------

#define BATCH 4
#define SEQ   2048
#define DM    1024
#define DI    2048
#define DS    64
#define MTOK  (BATCH * SEQ)   // 8192
#define NCH   16
#define CHUNK 128

// ------------------------- scratch (device globals) ------------------------
__device__ float g_xi[MTOK * DI];
__device__ float g_sz[MTOK * DI];
__device__ float g_a[MTOK];
__device__ float g_Braw[MTOK * DS];
__device__ float g_Craw[MTOK * DS];
__device__ float g_B[MTOK * DI];
__device__ float g_C[MTOK * DI];
__device__ float g_y[MTOK * DI];
__device__ float g_Hend[BATCH * NCH * DI];
__device__ float g_Hcarry[BATCH * NCH * DI];
__device__ float g_Aprod[BATCH * NCH];
// transposed + split weights: [N, K] bf16 hi/lo
__device__ __nv_bfloat16 g_Wih[(2 * DI) * DM];   // W_in^T  [4096,1024]
__device__ __nv_bfloat16 g_Wil[(2 * DI) * DM];
__device__ __nv_bfloat16 g_Woh[DM * DI];         // W_out^T [1024,2048]
__device__ __nv_bfloat16 g_Wol[DM * DI];

// ------------------------------ PTX helpers --------------------------------
__device__ __forceinline__ uint32_t smem_u32(const void* p) {
    uint32_t a;
    asm("{ .reg .u64 t; cvta.to.shared.u64 t, %1; cvt.u32.u64 %0, t; }"
        : "=r"(a) : "l"(p));
    return a;
}

__device__ __forceinline__ void mma16816(float* d, const uint32_t* a, const uint32_t* b) {
    asm volatile(
        "mma.sync.aligned.m16n8k16.row.col.f32.bf16.bf16.f32 "
        "{%0,%1,%2,%3}, {%4,%5,%6,%7}, {%8,%9}, {%0,%1,%2,%3};"
        : "+f"(d[0]), "+f"(d[1]), "+f"(d[2]), "+f"(d[3])
        : "r"(a[0]), "r"(a[1]), "r"(a[2]), "r"(a[3]), "r"(b[0]), "r"(b[1]));
}

__device__ __forceinline__ void ldsm4(uint32_t* r, uint32_t addr) {
    asm volatile("ldmatrix.sync.aligned.m8n8.x4.shared.b16 {%0,%1,%2,%3}, [%4];"
                 : "=r"(r[0]), "=r"(r[1]), "=r"(r[2]), "=r"(r[3]) : "r"(addr));
}
__device__ __forceinline__ void ldsm2(uint32_t* r, uint32_t addr) {
    asm volatile("ldmatrix.sync.aligned.m8n8.x2.shared.b16 {%0,%1}, [%2];"
                 : "=r"(r[0]), "=r"(r[1]) : "r"(addr));
}

__device__ __forceinline__ uint32_t pack_bf2(float a, float b) {
    __nv_bfloat162 t = __floats2bfloat162_rn(a, b);
    return *(uint32_t*)&t;
}

// --------------------- mma.sync split-bf16 GEMM core -----------------------
// C[M,N] = A[M,K](fp32) @ Bt[N,K](bf16 hi/lo)^T.
// CTA tile 128x64, BK=32; 8 warps: warpM=wid>>1 (4), warpN=wid&1 (2),
// warp tile 32x32 (2 m-tiles x 4 n-tiles of m16n8).
// SMEM rows padded to 40 bf16 (80B = 5*16B): ldmatrix conflict-free.
// EPI 0: store fp32 to Cout.  EPI 1: xi (cols<DI) / silu -> g_sz.
#define KPAD 40

template<int EPI>
__device__ void mma_gemm_dev(const float* __restrict__ A,
                             const __nv_bfloat16* __restrict__ Bhi,
                             const __nv_bfloat16* __restrict__ Blo,
                             float* __restrict__ Cout, int N, int K)
{
    __shared__ __align__(16) __nv_bfloat16 sAh[128 * KPAD];
    __shared__ __align__(16) __nv_bfloat16 sAl[128 * KPAD];
    __shared__ __align__(16) __nv_bfloat16 sBh[64 * KPAD];
    __shared__ __align__(16) __nv_bfloat16 sBl[64 * KPAD];

    const int tid  = threadIdx.x;
    const int wid  = tid >> 5;
    const int lane = tid & 31;
    const int warpM = wid >> 1;       // 0..3
    const int warpN = wid & 1;        // 0..1
    const int rowBase = blockIdx.y * 128;
    const int colBase = blockIdx.x * 64;
    const int NC = K / 32;

    const uint32_t ahB = smem_u32(sAh);
    const uint32_t alB = smem_u32(sAl);
    const uint32_t bhB = smem_u32(sBh);
    const uint32_t blB = smem_u32(sBl);

    float acc[2][4][4];
#pragma unroll
    for (int i = 0; i < 2; i++)
#pragma unroll
        for (int j = 0; j < 4; j++)
#pragma unroll
            for (int q = 0; q < 4; q++) acc[i][j][q] = 0.f;

    // per-thread load coords
    const int lr = tid >> 1, lh = tid & 1;          // A: row, k-half (16 floats)
    const int br = tid >> 2, bq = tid & 3;          // B: row, uint4 index

    for (int c = 0; c < NC; ++c) {
        __syncthreads();
        // ---- A chunk: 128 x 32 fp32 -> hi/lo bf16 ----
        {
            const float* ap = A + (size_t)(rowBase + lr) * K + c * 32 + lh * 16;
            float4 v0 = *(const float4*)(ap + 0);
            float4 v1 = *(const float4*)(ap + 4);
            float4 v2 = *(const float4*)(ap + 8);
            float4 v3 = *(const float4*)(ap + 12);
            float f[16] = {v0.x,v0.y,v0.z,v0.w, v1.x,v1.y,v1.z,v1.w,
                           v2.x,v2.y,v2.z,v2.w, v3.x,v3.y,v3.z,v3.w};
            float hf[16], lf[16];
#pragma unroll
            for (int j = 0; j < 16; j++) {
                __nv_bfloat16 h = __float2bfloat16(f[j]);
                hf[j] = __bfloat162float(h);
                lf[j] = f[j] - hf[j];
            }
            uint4 h0, h1, l0, l1;
            h0.x = pack_bf2(hf[0], hf[1]);  h0.y = pack_bf2(hf[2], hf[3]);
            h0.z = pack_bf2(hf[4], hf[5]);  h0.w = pack_bf2(hf[6], hf[7]);
            h1.x = pack_bf2(hf[8], hf[9]);  h1.y = pack_bf2(hf[10], hf[11]);
            h1.z = pack_bf2(hf[12], hf[13]);h1.w = pack_bf2(hf[14], hf[15]);
            l0.x = pack_bf2(lf[0], lf[1]);  l0.y = pack_bf2(lf[2], lf[3]);
            l0.z = pack_bf2(lf[4], lf[5]);  l0.w = pack_bf2(lf[6], lf[7]);
            l1.x = pack_bf2(lf[8], lf[9]);  l1.y = pack_bf2(lf[10], lf[11]);
            l1.z = pack_bf2(lf[12], lf[13]);l1.w = pack_bf2(lf[14], lf[15]);
            const int so = lr * KPAD + lh * 16;
            *(uint4*)(sAh + so)     = h0;
            *(uint4*)(sAh + so + 8) = h1;
            *(uint4*)(sAl + so)     = l0;
            *(uint4*)(sAl + so + 8) = l1;
        }
        // ---- B chunk: 64 x 32 bf16 (hi & lo) ----
        {
            const size_t go = (size_t)(colBase + br) * K + c * 32 + bq * 8;
            uint4 vh = *(const uint4*)(Bhi + go);
            uint4 vl = *(const uint4*)(Blo + go);
            const int so = br * KPAD + bq * 8;
            *(uint4*)(sBh + so) = vh;
            *(uint4*)(sBl + so) = vl;
        }
        __syncthreads();

        // ---- MMA over 2 k-steps of 16 ----
#pragma unroll
        for (int ks = 0; ks < 2; ks++) {
            const int k0 = ks * 16;
            uint32_t ah[2][4], al[2][4], bh[4][2], bl[4][2];
#pragma unroll
            for (int mi = 0; mi < 2; mi++) {
                const int m0 = warpM * 32 + mi * 16;
                const uint32_t off =
                    (uint32_t)(((m0 + (lane & 15)) * KPAD + k0 + (lane >> 4) * 8) * 2);
                ldsm4(ah[mi], ahB + off);
                ldsm4(al[mi], alB + off);
            }
#pragma unroll
            for (int nj = 0; nj < 4; nj++) {
                const int n0 = warpN * 32 + nj * 8;
                const uint32_t off =
                    (uint32_t)(((n0 + (lane & 7)) * KPAD + k0 + ((lane >> 3) & 1) * 8) * 2);
                ldsm2(bh[nj], bhB + off);
                ldsm2(bl[nj], blB + off);
            }
#pragma unroll
            for (int mi = 0; mi < 2; mi++)
#pragma unroll
                for (int nj = 0; nj < 4; nj++) {
                    mma16816(acc[mi][nj], ah[mi], bh[nj]);
                    mma16816(acc[mi][nj], ah[mi], bl[nj]);
                    mma16816(acc[mi][nj], al[mi], bh[nj]);
                }
        }
    }

    // ---- epilogue: fragment layout (m16n8): c0,c1 = (qr, 2qc), c2,c3 = (+8) ----
    const int qr = lane >> 2, qc = lane & 3;
#pragma unroll
    for (int mi = 0; mi < 2; mi++) {
#pragma unroll
        for (int nj = 0; nj < 4; nj++) {
            const int m0 = rowBase + warpM * 32 + mi * 16;
            const int nn = warpN * 32 + nj * 8 + qc * 2;
            float c0 = acc[mi][nj][0], c1 = acc[mi][nj][1];
            float c2 = acc[mi][nj][2], c3 = acc[mi][nj][3];
            if (EPI == 0) {
                float* p0 = Cout + (size_t)(m0 + qr) * N + colBase + nn;
                float* p1 = Cout + (size_t)(m0 + qr + 8) * N + colBase + nn;
                *(float2*)p0 = make_float2(c0, c1);
                *(float2*)p1 = make_float2(c2, c3);
            } else {
                const bool zside = (colBase >= DI);
                const int cb = (zside ? colBase - DI : colBase) + nn;
                float* base = zside ? g_sz : g_xi;
                if (zside) {
                    c0 = c0 / (1.f + expf(-c0));
                    c1 = c1 / (1.f + expf(-c1));
                    c2 = c2 / (1.f + expf(-c2));
                    c3 = c3 / (1.f + expf(-c3));
                }
                *(float2*)(base + (size_t)(m0 + qr) * DI + cb)     = make_float2(c0, c1);
                *(float2*)(base + (size_t)(m0 + qr + 8) * DI + cb) = make_float2(c2, c3);
            }
        }
    }
}

__global__ __launch_bounds__(256, 2)
void k_mma_in(const float* __restrict__ x)
{
    mma_gemm_dev<1>(x, g_Wih, g_Wil, nullptr, 2 * DI, DM);
}

__global__ __launch_bounds__(256, 2)
void k_mma_out(float* __restrict__ out)
{
    mma_gemm_dev<0>(g_y, g_Woh, g_Wol, out, DM, DI);
}

// -------------------- weight transpose + bf16 hi/lo split -------------------
__device__ void wsplit_dev(const float* __restrict__ W,
                           __nv_bfloat16* __restrict__ Thi,
                           __nv_bfloat16* __restrict__ Tlo, int K, int N)
{
    __shared__ float ts[32][33];
    const int n0 = blockIdx.x * 32, k0 = blockIdx.y * 32;
    const int tx = threadIdx.x, ty = threadIdx.y;
    for (int i = ty; i < 32; i += 8)
        ts[i][tx] = W[(size_t)(k0 + i) * N + n0 + tx];
    __syncthreads();
    for (int i = ty; i < 32; i += 8) {
        float v = ts[tx][i];
        __nv_bfloat16 h = __float2bfloat16(v);
        float lf = v - __bfloat162float(h);
        size_t o = (size_t)(n0 + i) * K + k0 + tx;
        Thi[o] = h;
        Tlo[o] = __float2bfloat16(lf);
    }
}

__global__ __launch_bounds__(256)
void k_wsplit_in(const float* __restrict__ W) { wsplit_dev(W, g_Wih, g_Wil, DM, 2 * DI); }
__global__ __launch_bounds__(256)
void k_wsplit_out(const float* __restrict__ W) { wsplit_dev(W, g_Woh, g_Wol, DI, DM); }

// ------------------------ SIMT SGEMM (B/C expansion) ------------------------
#define BM 128
#define BN 128
#define BKK 8
__device__ __forceinline__
void sgemm_dev(const float* __restrict__ A, const float* __restrict__ B,
               float* __restrict__ C0, int N, int K)
{
    __shared__ float As[BKK][BM];
    __shared__ float Bs[BKK][BN];
    const int tid = threadIdx.x;
    const int rowBase = blockIdx.y * BM;
    const int colBase = blockIdx.x * BN;
    const int aRow = tid >> 1, aK = (tid & 1) * 4;
    const int bK = tid >> 5, bCol = (tid & 31) * 4;
    const float* Aptr = A + (size_t)(rowBase + aRow) * K + aK;
    const float* Bptr = B + (size_t)bK * N + colBase + bCol;
    const int ty = tid >> 4, tx = tid & 15;

    float acc[8][8];
#pragma unroll
    for (int i = 0; i < 8; i++)
#pragma unroll
        for (int j = 0; j < 8; j++) acc[i][j] = 0.f;

    for (int k0 = 0; k0 < K; k0 += BKK) {
        float4 av = *(const float4*)(Aptr + k0);
        float4 bv = *(const float4*)(Bptr + (size_t)k0 * N);
        __syncthreads();
        As[aK + 0][aRow] = av.x; As[aK + 1][aRow] = av.y;
        As[aK + 2][aRow] = av.z; As[aK + 3][aRow] = av.w;
        *(float4*)&Bs[bK][bCol] = bv;
        __syncthreads();
#pragma unroll
        for (int kk = 0; kk < BKK; kk++) {
            float4 a0 = *(const float4*)(&As[kk][ty * 8]);
            float4 a1 = *(const float4*)(&As[kk][ty * 8 + 4]);
            float4 b0 = *(const float4*)(&Bs[kk][tx * 8]);
            float4 b1 = *(const float4*)(&Bs[kk][tx * 8 + 4]);
            float ar[8] = {a0.x, a0.y, a0.z, a0.w, a1.x, a1.y, a1.z, a1.w};
            float br[8] = {b0.x, b0.y, b0.z, b0.w, b1.x, b1.y, b1.z, b1.w};
#pragma unroll
            for (int i = 0; i < 8; i++)
#pragma unroll
                for (int j = 0; j < 8; j++)
                    acc[i][j] = fmaf(ar[i], br[j], acc[i][j]);
        }
    }
#pragma unroll
    for (int i = 0; i < 8; i++) {
        int row = rowBase + ty * 8 + i;
        float* cp = C0 + (size_t)row * N + colBase + tx * 8;
        *(float4*)cp       = make_float4(acc[i][0], acc[i][1], acc[i][2], acc[i][3]);
        *(float4*)(cp + 4) = make_float4(acc[i][4], acc[i][5], acc[i][6], acc[i][7]);
    }
}

__global__ __launch_bounds__(256)
void k_gemm_bc(const float* __restrict__ W_B, const float* __restrict__ W_C)
{
    if (blockIdx.z == 0) sgemm_dev(g_Braw, W_B, g_B, DI, DS);
    else                 sgemm_dev(g_Craw, W_C, g_C, DI, DS);
}

// ------------------------- proj = xi @ W_xp (N=129) ------------------------
#define PRT 32
#define PKT 32
__global__ __launch_bounds__(160)
void proj_kernel(const float* __restrict__ Wxp, const float* __restrict__ A_log)
{
    __shared__ float xs[PKT][PRT + 4];
    const int tid = threadIdx.x;
    const int row0 = blockIdx.x * PRT;
    const int col = tid;
    const bool active = (col < 129);

    float acc[PRT];
#pragma unroll
    for (int r = 0; r < PRT; r++) acc[r] = 0.f;

    for (int k0 = 0; k0 < DI; k0 += PKT) {
        __syncthreads();
        for (int i = tid; i < PRT * PKT; i += 160) {
            int r = i >> 5, c = i & 31;
            xs[c][r] = g_xi[(size_t)(row0 + r) * DI + k0 + c];
        }
        __syncthreads();
        float wv[PKT];
        if (active) {
#pragma unroll
            for (int kk = 0; kk < PKT; kk++)
                wv[kk] = Wxp[(size_t)(k0 + kk) * 129 + col];
        } else {
#pragma unroll
            for (int kk = 0; kk < PKT; kk++) wv[kk] = 0.f;
        }
#pragma unroll
        for (int kk = 0; kk < PKT; kk++) {
            float w = wv[kk];
#pragma unroll
            for (int r4 = 0; r4 < PRT / 4; r4++) {
                float4 xv = *(const float4*)(&xs[kk][r4 * 4]);
                acc[r4*4+0] = fmaf(xv.x, w, acc[r4*4+0]);
                acc[r4*4+1] = fmaf(xv.y, w, acc[r4*4+1]);
                acc[r4*4+2] = fmaf(xv.z, w, acc[r4*4+2]);
                acc[r4*4+3] = fmaf(xv.w, w, acc[r4*4+3]);
            }
        }
    }

    if (active) {
        float Aval = -expf(*A_log);
#pragma unroll 4
        for (int r = 0; r < PRT; r++) {
            int m = row0 + r;
            float v = acc[r];
            if (col == 0) {
                float dlt = (v > 20.f) ? v : log1pf(expf(v));
                g_a[m] = expf(Aval * dlt);
            } else if (col <= DS) {
                g_Braw[(size_t)m * DS + (col - 1)] = v;
            } else {
                g_Craw[(size_t)m * DS + (col - 1 - DS)] = v;
            }
        }
    }
}

// ------------------------------- 3-phase scan ------------------------------
__global__ __launch_bounds__(256)
void scan_chunk_kernel()
{
    __shared__ float as_[CHUNK];
    const int d = blockIdx.x * blockDim.x + threadIdx.x;
    const int c = blockIdx.y, b = blockIdx.z;
    const int m0 = b * SEQ + c * CHUNK;
    if (threadIdx.x < CHUNK) as_[threadIdx.x] = g_a[m0 + threadIdx.x];
    __syncthreads();

    const float* bp = g_B  + (size_t)m0 * DI + d;
    const float* xp = g_xi + (size_t)m0 * DI + d;
    float h = 0.f;
#pragma unroll 4
    for (int t = 0; t < CHUNK; t++)
        h = fmaf(as_[t], h, bp[(size_t)t * DI] * xp[(size_t)t * DI]);

    g_Hend[((size_t)(b * NCH + c)) * DI + d] = h;
    if (blockIdx.x == 0 && threadIdx.x == 0) {
        float ap = 1.f;
#pragma unroll
        for (int t = 0; t < CHUNK; t++) ap *= as_[t];
        g_Aprod[b * NCH + c] = ap;
    }
}

__global__ __launch_bounds__(256)
void scan_carry_kernel()
{
    const int idx = blockIdx.x * blockDim.x + threadIdx.x;
    const int b = idx / DI, d = idx % DI;
    float carry = 0.f;
#pragma unroll
    for (int c = 0; c < NCH; c++) {
        size_t o = ((size_t)(b * NCH + c)) * DI + d;
        g_Hcarry[o] = carry;
        carry = fmaf(g_Aprod[b * NCH + c], carry, g_Hend[o]);
    }
}

__global__ __launch_bounds__(256)
void scan_final_kernel(const float* __restrict__ Dvec)
{
    __shared__ float as_[CHUNK];
    const int d = blockIdx.x * blockDim.x + threadIdx.x;
    const int c = blockIdx.y, b = blockIdx.z;
    const int m0 = b * SEQ + c * CHUNK;
    if (threadIdx.x < CHUNK) as_[threadIdx.x] = g_a[m0 + threadIdx.x];
    __syncthreads();

    const float* bp  = g_B  + (size_t)m0 * DI + d;
    const float* xp  = g_xi + (size_t)m0 * DI + d;
    const float* cp  = g_C  + (size_t)m0 * DI + d;
    const float* szp = g_sz + (size_t)m0 * DI + d;
    float*       yp  = g_y  + (size_t)m0 * DI + d;

    const float Dd = Dvec[d];
    float h = g_Hcarry[((size_t)(b * NCH + c)) * DI + d];
#pragma unroll 4
    for (int t = 0; t < CHUNK; t++) {
        float xv = xp[(size_t)t * DI];
        h = fmaf(as_[t], h, bp[(size_t)t * DI] * xv);
        float yv = fmaf(cp[(size_t)t * DI], h, Dd * xv);
        yp[(size_t)t * DI] = yv * szp[(size_t)t * DI];
    }
}

// --------------------------------- launch ----------------------------------
extern "C" void kernel_launch(void* const* d_in, const int* in_sizes, int n_in,
                              void* d_out, int out_size)
{
    const float* x     = (const float*)d_in[0];
    const float* W_in  = (const float*)d_in[1];
    const float* W_xp  = (const float*)d_in[2];
    const float* W_B   = (const float*)d_in[3];
    const float* W_C   = (const float*)d_in[4];
    const float* W_out = (const float*)d_in[5];
    const float* Dvec  = (const float*)d_in[6];
    const float* A_log = (const float*)d_in[7];
    float* out = (float*)d_out;

    // 0) weight transpose + hi/lo split
    k_wsplit_in <<<dim3((2 * DI) / 32, DM / 32), dim3(32, 8)>>>(W_in);
    k_wsplit_out<<<dim3(DM / 32, DI / 32),      dim3(32, 8)>>>(W_out);
    // 1) xz = x @ W_in -> xi, silu(z)   [mma.sync bf16 split]
    k_mma_in<<<dim3((2 * DI) / 64, MTOK / 128), 256>>>(x);
    // 2) proj = xi @ W_xp -> a, B_raw, C_raw
    proj_kernel<<<MTOK / PRT, 160>>>(W_xp, A_log);
    // 3) B = B_raw @ W_B ; C = C_raw @ W_C
    k_gemm_bc<<<dim3(DI / BN, MTOK / BM, 2), 256>>>(W_B, W_C);
    // 4) chunked scan + gating -> y
    scan_chunk_kernel<<<dim3(DI / 256, NCH, BATCH), 256>>>();
    scan_carry_kernel<<<(BATCH * DI) / 256, 256>>>();
    scan_final_kernel<<<dim3(DI / 256, NCH, BATCH), 256>>>(Dvec);
    // 5) out = y @ W_out   [mma.sync bf16 split]
    k_mma_out<<<dim3(DM / 64, MTOK / 128), 256>>>(out);
}

// round 12
// speedup vs baseline: 2.9015x; 1.1373x over previous
#include <cuda_runtime.h>
#include <cuda_bf16.h>
#include <math.h>
#include <stdint.h>

// ---------------------------------------------------------------------------
// MambaSSD — split-bf16 mma.sync for x@W_in, y@W_out, and xi@W_xp (proj).
// out = ((C*h + D*xi) * silu(z)) @ W_out
// ---------------------------------------------------------------------------

#define BATCH 4
#define SEQ   2048
#define DM    1024
#define DI    2048
#define DS    64
#define MTOK  (BATCH * SEQ)   // 8192
#define NCH   16
#define CHUNK 128

// ------------------------- scratch (device globals) ------------------------
__device__ float g_xi[MTOK * DI];
__device__ float g_sz[MTOK * DI];
__device__ float g_a[MTOK];
__device__ float g_Braw[MTOK * DS];
__device__ float g_Craw[MTOK * DS];
__device__ float g_B[MTOK * DI];
__device__ float g_C[MTOK * DI];
__device__ float g_y[MTOK * DI];
__device__ float g_Hend[BATCH * NCH * DI];
__device__ float g_Hcarry[BATCH * NCH * DI];
__device__ float g_Aprod[BATCH * NCH];
// transposed + split weights: [N, K] bf16 hi/lo
__device__ __nv_bfloat16 g_Wih[(2 * DI) * DM];   // W_in^T  [4096,1024]
__device__ __nv_bfloat16 g_Wil[(2 * DI) * DM];
__device__ __nv_bfloat16 g_Woh[DM * DI];         // W_out^T [1024,2048]
__device__ __nv_bfloat16 g_Wol[DM * DI];
#define PN 144                                    // padded N for proj (129->144)
__device__ __nv_bfloat16 g_Wxh[PN * DI];         // W_xp^T  [144,2048] (pad=0)
__device__ __nv_bfloat16 g_Wxl[PN * DI];

// ------------------------------ PTX helpers --------------------------------
__device__ __forceinline__ uint32_t smem_u32(const void* p) {
    uint32_t a;
    asm("{ .reg .u64 t; cvta.to.shared.u64 t, %1; cvt.u32.u64 %0, t; }"
        : "=r"(a) : "l"(p));
    return a;
}

__device__ __forceinline__ void mma16816(float* d, const uint32_t* a, const uint32_t* b) {
    asm volatile(
        "mma.sync.aligned.m16n8k16.row.col.f32.bf16.bf16.f32 "
        "{%0,%1,%2,%3}, {%4,%5,%6,%7}, {%8,%9}, {%0,%1,%2,%3};"
        : "+f"(d[0]), "+f"(d[1]), "+f"(d[2]), "+f"(d[3])
        : "r"(a[0]), "r"(a[1]), "r"(a[2]), "r"(a[3]), "r"(b[0]), "r"(b[1]));
}

__device__ __forceinline__ void ldsm4(uint32_t* r, uint32_t addr) {
    asm volatile("ldmatrix.sync.aligned.m8n8.x4.shared.b16 {%0,%1,%2,%3}, [%4];"
                 : "=r"(r[0]), "=r"(r[1]), "=r"(r[2]), "=r"(r[3]) : "r"(addr));
}
__device__ __forceinline__ void ldsm2(uint32_t* r, uint32_t addr) {
    asm volatile("ldmatrix.sync.aligned.m8n8.x2.shared.b16 {%0,%1}, [%2];"
                 : "=r"(r[0]), "=r"(r[1]) : "r"(addr));
}

__device__ __forceinline__ uint32_t pack_bf2(float a, float b) {
    __nv_bfloat162 t = __floats2bfloat162_rn(a, b);
    return *(uint32_t*)&t;
}

#define KPAD 40   // smem row stride in bf16 (80B = 5*16B): conflict-free ldmatrix

// --------------------- mma.sync split-bf16 GEMM core -----------------------
// C[M,N] = A[M,K](fp32) @ Bt[N,K](bf16 hi/lo)^T.
// CTA tile 128x64, BK=32; 8 warps: 4M x 2N, warp tile 32x32.
// EPI 0: store fp32 to Cout.  EPI 1: xi (cols<DI) / silu -> g_sz.
template<int EPI>
__device__ void mma_gemm_dev(const float* __restrict__ A,
                             const __nv_bfloat16* __restrict__ Bhi,
                             const __nv_bfloat16* __restrict__ Blo,
                             float* __restrict__ Cout, int N, int K)
{
    __shared__ __align__(16) __nv_bfloat16 sAh[128 * KPAD];
    __shared__ __align__(16) __nv_bfloat16 sAl[128 * KPAD];
    __shared__ __align__(16) __nv_bfloat16 sBh[64 * KPAD];
    __shared__ __align__(16) __nv_bfloat16 sBl[64 * KPAD];

    const int tid  = threadIdx.x;
    const int wid  = tid >> 5;
    const int lane = tid & 31;
    const int warpM = wid >> 1;
    const int warpN = wid & 1;
    const int rowBase = blockIdx.y * 128;
    const int colBase = blockIdx.x * 64;
    const int NC = K / 32;

    const uint32_t ahB = smem_u32(sAh);
    const uint32_t alB = smem_u32(sAl);
    const uint32_t bhB = smem_u32(sBh);
    const uint32_t blB = smem_u32(sBl);

    float acc[2][4][4];
#pragma unroll
    for (int i = 0; i < 2; i++)
#pragma unroll
        for (int j = 0; j < 4; j++)
#pragma unroll
            for (int q = 0; q < 4; q++) acc[i][j][q] = 0.f;

    const int lr = tid >> 1, lh = tid & 1;
    const int br = tid >> 2, bq = tid & 3;

    for (int c = 0; c < NC; ++c) {
        __syncthreads();
        {
            const float* ap = A + (size_t)(rowBase + lr) * K + c * 32 + lh * 16;
            float4 v0 = *(const float4*)(ap + 0);
            float4 v1 = *(const float4*)(ap + 4);
            float4 v2 = *(const float4*)(ap + 8);
            float4 v3 = *(const float4*)(ap + 12);
            float f[16] = {v0.x,v0.y,v0.z,v0.w, v1.x,v1.y,v1.z,v1.w,
                           v2.x,v2.y,v2.z,v2.w, v3.x,v3.y,v3.z,v3.w};
            float hf[16], lf[16];
#pragma unroll
            for (int j = 0; j < 16; j++) {
                __nv_bfloat16 h = __float2bfloat16(f[j]);
                hf[j] = __bfloat162float(h);
                lf[j] = f[j] - hf[j];
            }
            uint4 h0, h1, l0, l1;
            h0.x = pack_bf2(hf[0], hf[1]);  h0.y = pack_bf2(hf[2], hf[3]);
            h0.z = pack_bf2(hf[4], hf[5]);  h0.w = pack_bf2(hf[6], hf[7]);
            h1.x = pack_bf2(hf[8], hf[9]);  h1.y = pack_bf2(hf[10], hf[11]);
            h1.z = pack_bf2(hf[12], hf[13]);h1.w = pack_bf2(hf[14], hf[15]);
            l0.x = pack_bf2(lf[0], lf[1]);  l0.y = pack_bf2(lf[2], lf[3]);
            l0.z = pack_bf2(lf[4], lf[5]);  l0.w = pack_bf2(lf[6], lf[7]);
            l1.x = pack_bf2(lf[8], lf[9]);  l1.y = pack_bf2(lf[10], lf[11]);
            l1.z = pack_bf2(lf[12], lf[13]);l1.w = pack_bf2(lf[14], lf[15]);
            const int so = lr * KPAD + lh * 16;
            *(uint4*)(sAh + so)     = h0;
            *(uint4*)(sAh + so + 8) = h1;
            *(uint4*)(sAl + so)     = l0;
            *(uint4*)(sAl + so + 8) = l1;
        }
        {
            const size_t go = (size_t)(colBase + br) * K + c * 32 + bq * 8;
            uint4 vh = *(const uint4*)(Bhi + go);
            uint4 vl = *(const uint4*)(Blo + go);
            const int so = br * KPAD + bq * 8;
            *(uint4*)(sBh + so) = vh;
            *(uint4*)(sBl + so) = vl;
        }
        __syncthreads();

#pragma unroll
        for (int ks = 0; ks < 2; ks++) {
            const int k0 = ks * 16;
            uint32_t ah[2][4], al[2][4], bh[4][2], bl[4][2];
#pragma unroll
            for (int mi = 0; mi < 2; mi++) {
                const int m0 = warpM * 32 + mi * 16;
                const uint32_t off =
                    (uint32_t)(((m0 + (lane & 15)) * KPAD + k0 + (lane >> 4) * 8) * 2);
                ldsm4(ah[mi], ahB + off);
                ldsm4(al[mi], alB + off);
            }
#pragma unroll
            for (int nj = 0; nj < 4; nj++) {
                const int n0 = warpN * 32 + nj * 8;
                const uint32_t off =
                    (uint32_t)(((n0 + (lane & 7)) * KPAD + k0 + ((lane >> 3) & 1) * 8) * 2);
                ldsm2(bh[nj], bhB + off);
                ldsm2(bl[nj], blB + off);
            }
#pragma unroll
            for (int mi = 0; mi < 2; mi++)
#pragma unroll
                for (int nj = 0; nj < 4; nj++) {
                    mma16816(acc[mi][nj], ah[mi], bh[nj]);
                    mma16816(acc[mi][nj], ah[mi], bl[nj]);
                    mma16816(acc[mi][nj], al[mi], bh[nj]);
                }
        }
    }

    const int qr = lane >> 2, qc = lane & 3;
#pragma unroll
    for (int mi = 0; mi < 2; mi++) {
#pragma unroll
        for (int nj = 0; nj < 4; nj++) {
            const int m0 = rowBase + warpM * 32 + mi * 16;
            const int nn = warpN * 32 + nj * 8 + qc * 2;
            float c0 = acc[mi][nj][0], c1 = acc[mi][nj][1];
            float c2 = acc[mi][nj][2], c3 = acc[mi][nj][3];
            if (EPI == 0) {
                float* p0 = Cout + (size_t)(m0 + qr) * N + colBase + nn;
                float* p1 = Cout + (size_t)(m0 + qr + 8) * N + colBase + nn;
                *(float2*)p0 = make_float2(c0, c1);
                *(float2*)p1 = make_float2(c2, c3);
            } else {
                const bool zside = (colBase >= DI);
                const int cb = (zside ? colBase - DI : colBase) + nn;
                float* base = zside ? g_sz : g_xi;
                if (zside) {
                    c0 = c0 / (1.f + expf(-c0));
                    c1 = c1 / (1.f + expf(-c1));
                    c2 = c2 / (1.f + expf(-c2));
                    c3 = c3 / (1.f + expf(-c3));
                }
                *(float2*)(base + (size_t)(m0 + qr) * DI + cb)     = make_float2(c0, c1);
                *(float2*)(base + (size_t)(m0 + qr + 8) * DI + cb) = make_float2(c2, c3);
            }
        }
    }
}

__global__ __launch_bounds__(256, 2)
void k_mma_in(const float* __restrict__ x)
{
    mma_gemm_dev<1>(x, g_Wih, g_Wil, nullptr, 2 * DI, DM);
}

__global__ __launch_bounds__(256, 2)
void k_mma_out(float* __restrict__ out)
{
    mma_gemm_dev<0>(g_y, g_Woh, g_Wol, out, DM, DI);
}

// ----------------- proj = xi @ W_xp via mma.sync (N pad 144) ----------------
// CTA tile 128 x 144, K=2048, 8 warps: 4M x 2N, warp tile 32 x 72 (9 n-tiles).
// Epilogue scatters: col0 -> softplus/exp -> g_a, 1..64 -> Braw, 65..128 -> Craw.
__device__ __forceinline__ void proj_store(int m, int col, float v, float Aval)
{
    if (col == 0) {
        float dlt = (v > 20.f) ? v : log1pf(expf(v));
        g_a[m] = expf(Aval * dlt);
    } else if (col <= DS) {
        g_Braw[(size_t)m * DS + (col - 1)] = v;
    } else if (col <= 2 * DS) {
        g_Craw[(size_t)m * DS + (col - 1 - DS)] = v;
    }
}

__global__ __launch_bounds__(256, 1)
void k_proj_mma(const float* __restrict__ A_log)
{
    __shared__ __align__(16) __nv_bfloat16 sAh[128 * KPAD];
    __shared__ __align__(16) __nv_bfloat16 sAl[128 * KPAD];
    __shared__ __align__(16) __nv_bfloat16 sBh[PN * KPAD];
    __shared__ __align__(16) __nv_bfloat16 sBl[PN * KPAD];

    const int tid  = threadIdx.x;
    const int wid  = tid >> 5;
    const int lane = tid & 31;
    const int warpM = wid >> 1;       // 0..3
    const int warpN = wid & 1;        // 0..1
    const int rowBase = blockIdx.x * 128;
    const int NC = DI / 32;           // 64 chunks

    const uint32_t ahB = smem_u32(sAh);
    const uint32_t alB = smem_u32(sAl);
    const uint32_t bhB = smem_u32(sBh);
    const uint32_t blB = smem_u32(sBl);

    float acc[2][9][4];
#pragma unroll
    for (int i = 0; i < 2; i++)
#pragma unroll
        for (int j = 0; j < 9; j++)
#pragma unroll
            for (int q = 0; q < 4; q++) acc[i][j][q] = 0.f;

    const int lr = tid >> 1, lh = tid & 1;

    for (int c = 0; c < NC; ++c) {
        __syncthreads();
        // A chunk: 128 x 32 fp32 (g_xi) -> hi/lo bf16
        {
            const float* ap = g_xi + (size_t)(rowBase + lr) * DI + c * 32 + lh * 16;
            float4 v0 = *(const float4*)(ap + 0);
            float4 v1 = *(const float4*)(ap + 4);
            float4 v2 = *(const float4*)(ap + 8);
            float4 v3 = *(const float4*)(ap + 12);
            float f[16] = {v0.x,v0.y,v0.z,v0.w, v1.x,v1.y,v1.z,v1.w,
                           v2.x,v2.y,v2.z,v2.w, v3.x,v3.y,v3.z,v3.w};
            float hf[16], lf[16];
#pragma unroll
            for (int j = 0; j < 16; j++) {
                __nv_bfloat16 h = __float2bfloat16(f[j]);
                hf[j] = __bfloat162float(h);
                lf[j] = f[j] - hf[j];
            }
            uint4 h0, h1, l0, l1;
            h0.x = pack_bf2(hf[0], hf[1]);  h0.y = pack_bf2(hf[2], hf[3]);
            h0.z = pack_bf2(hf[4], hf[5]);  h0.w = pack_bf2(hf[6], hf[7]);
            h1.x = pack_bf2(hf[8], hf[9]);  h1.y = pack_bf2(hf[10], hf[11]);
            h1.z = pack_bf2(hf[12], hf[13]);h1.w = pack_bf2(hf[14], hf[15]);
            l0.x = pack_bf2(lf[0], lf[1]);  l0.y = pack_bf2(lf[2], lf[3]);
            l0.z = pack_bf2(lf[4], lf[5]);  l0.w = pack_bf2(lf[6], lf[7]);
            l1.x = pack_bf2(lf[8], lf[9]);  l1.y = pack_bf2(lf[10], lf[11]);
            l1.z = pack_bf2(lf[12], lf[13]);l1.w = pack_bf2(lf[14], lf[15]);
            const int so = lr * KPAD + lh * 16;
            *(uint4*)(sAh + so)     = h0;
            *(uint4*)(sAh + so + 8) = h1;
            *(uint4*)(sAl + so)     = l0;
            *(uint4*)(sAl + so + 8) = l1;
        }
        // B chunk: PN(144) x 32 bf16 hi/lo
        for (int i = tid; i < PN * 4; i += 256) {
            const int row = i >> 2, q = i & 3;
            const size_t go = (size_t)row * DI + c * 32 + q * 8;
            uint4 vh = *(const uint4*)(g_Wxh + go);
            uint4 vl = *(const uint4*)(g_Wxl + go);
            const int so = row * KPAD + q * 8;
            *(uint4*)(sBh + so) = vh;
            *(uint4*)(sBl + so) = vl;
        }
        __syncthreads();

#pragma unroll
        for (int ks = 0; ks < 2; ks++) {
            const int k0 = ks * 16;
            uint32_t ah[2][4], al[2][4];
#pragma unroll
            for (int mi = 0; mi < 2; mi++) {
                const int m0 = warpM * 32 + mi * 16;
                const uint32_t off =
                    (uint32_t)(((m0 + (lane & 15)) * KPAD + k0 + (lane >> 4) * 8) * 2);
                ldsm4(ah[mi], ahB + off);
                ldsm4(al[mi], alB + off);
            }
#pragma unroll
            for (int nj = 0; nj < 9; nj++) {
                const int n0 = warpN * 72 + nj * 8;
                const uint32_t off =
                    (uint32_t)(((n0 + (lane & 7)) * KPAD + k0 + ((lane >> 3) & 1) * 8) * 2);
                uint32_t bh[2], bl[2];
                ldsm2(bh, bhB + off);
                ldsm2(bl, blB + off);
#pragma unroll
                for (int mi = 0; mi < 2; mi++) {
                    mma16816(acc[mi][nj], ah[mi], bh);
                    mma16816(acc[mi][nj], ah[mi], bl);
                    mma16816(acc[mi][nj], al[mi], bh);
                }
            }
        }
    }

    const float Aval = -expf(*A_log);
    const int qr = lane >> 2, qc = lane & 3;
#pragma unroll
    for (int mi = 0; mi < 2; mi++) {
#pragma unroll
        for (int nj = 0; nj < 9; nj++) {
            const int m0 = rowBase + warpM * 32 + mi * 16;
            const int nn = warpN * 72 + nj * 8 + qc * 2;
            proj_store(m0 + qr,     nn,     acc[mi][nj][0], Aval);
            proj_store(m0 + qr,     nn + 1, acc[mi][nj][1], Aval);
            proj_store(m0 + qr + 8, nn,     acc[mi][nj][2], Aval);
            proj_store(m0 + qr + 8, nn + 1, acc[mi][nj][3], Aval);
        }
    }
}

// -------------------- weight transpose + bf16 hi/lo split -------------------
__device__ void wsplit_dev(const float* __restrict__ W,
                           __nv_bfloat16* __restrict__ Thi,
                           __nv_bfloat16* __restrict__ Tlo, int K, int N)
{
    __shared__ float ts[32][33];
    const int n0 = blockIdx.x * 32, k0 = blockIdx.y * 32;
    const int tx = threadIdx.x, ty = threadIdx.y;
    for (int i = ty; i < 32; i += 8)
        ts[i][tx] = W[(size_t)(k0 + i) * N + n0 + tx];
    __syncthreads();
    for (int i = ty; i < 32; i += 8) {
        float v = ts[tx][i];
        __nv_bfloat16 h = __float2bfloat16(v);
        float lf = v - __bfloat162float(h);
        size_t o = (size_t)(n0 + i) * K + k0 + tx;
        Thi[o] = h;
        Tlo[o] = __float2bfloat16(lf);
    }
}

__global__ __launch_bounds__(256)
void k_wsplit_in(const float* __restrict__ W) { wsplit_dev(W, g_Wih, g_Wil, DM, 2 * DI); }
__global__ __launch_bounds__(256)
void k_wsplit_out(const float* __restrict__ W) { wsplit_dev(W, g_Woh, g_Wol, DI, DM); }

// W_xp [2048,129] fp32 -> g_Wxh/g_Wxl [144,2048] bf16 (rows >= 129 zero)
__global__ __launch_bounds__(256)
void k_wsplit_xp(const float* __restrict__ Wxp)
{
    const int idx = blockIdx.x * 256 + threadIdx.x;
    if (idx >= PN * DI) return;
    const int n = idx / DI, k = idx % DI;
    float v = (n < 129) ? Wxp[(size_t)k * 129 + n] : 0.f;
    __nv_bfloat16 h = __float2bfloat16(v);
    float lf = v - __bfloat162float(h);
    g_Wxh[idx] = h;
    g_Wxl[idx] = __float2bfloat16(lf);
}

// ------------------------ SIMT SGEMM (B/C expansion) ------------------------
#define BM 128
#define BN 128
#define BKK 8
__device__ __forceinline__
void sgemm_dev(const float* __restrict__ A, const float* __restrict__ B,
               float* __restrict__ C0, int N, int K)
{
    __shared__ float As[BKK][BM];
    __shared__ float Bs[BKK][BN];
    const int tid = threadIdx.x;
    const int rowBase = blockIdx.y * BM;
    const int colBase = blockIdx.x * BN;
    const int aRow = tid >> 1, aK = (tid & 1) * 4;
    const int bK = tid >> 5, bCol = (tid & 31) * 4;
    const float* Aptr = A + (size_t)(rowBase + aRow) * K + aK;
    const float* Bptr = B + (size_t)bK * N + colBase + bCol;
    const int ty = tid >> 4, tx = tid & 15;

    float acc[8][8];
#pragma unroll
    for (int i = 0; i < 8; i++)
#pragma unroll
        for (int j = 0; j < 8; j++) acc[i][j] = 0.f;

    for (int k0 = 0; k0 < K; k0 += BKK) {
        float4 av = *(const float4*)(Aptr + k0);
        float4 bv = *(const float4*)(Bptr + (size_t)k0 * N);
        __syncthreads();
        As[aK + 0][aRow] = av.x; As[aK + 1][aRow] = av.y;
        As[aK + 2][aRow] = av.z; As[aK + 3][aRow] = av.w;
        *(float4*)&Bs[bK][bCol] = bv;
        __syncthreads();
#pragma unroll
        for (int kk = 0; kk < BKK; kk++) {
            float4 a0 = *(const float4*)(&As[kk][ty * 8]);
            float4 a1 = *(const float4*)(&As[kk][ty * 8 + 4]);
            float4 b0 = *(const float4*)(&Bs[kk][tx * 8]);
            float4 b1 = *(const float4*)(&Bs[kk][tx * 8 + 4]);
            float ar[8] = {a0.x, a0.y, a0.z, a0.w, a1.x, a1.y, a1.z, a1.w};
            float br[8] = {b0.x, b0.y, b0.z, b0.w, b1.x, b1.y, b1.z, b1.w};
#pragma unroll
            for (int i = 0; i < 8; i++)
#pragma unroll
                for (int j = 0; j < 8; j++)
                    acc[i][j] = fmaf(ar[i], br[j], acc[i][j]);
        }
    }
#pragma unroll
    for (int i = 0; i < 8; i++) {
        int row = rowBase + ty * 8 + i;
        float* cp = C0 + (size_t)row * N + colBase + tx * 8;
        *(float4*)cp       = make_float4(acc[i][0], acc[i][1], acc[i][2], acc[i][3]);
        *(float4*)(cp + 4) = make_float4(acc[i][4], acc[i][5], acc[i][6], acc[i][7]);
    }
}

__global__ __launch_bounds__(256)
void k_gemm_bc(const float* __restrict__ W_B, const float* __restrict__ W_C)
{
    if (blockIdx.z == 0) sgemm_dev(g_Braw, W_B, g_B, DI, DS);
    else                 sgemm_dev(g_Craw, W_C, g_C, DI, DS);
}

// ------------------------------- 3-phase scan ------------------------------
__global__ __launch_bounds__(256)
void scan_chunk_kernel()
{
    __shared__ float as_[CHUNK];
    const int d = blockIdx.x * blockDim.x + threadIdx.x;
    const int c = blockIdx.y, b = blockIdx.z;
    const int m0 = b * SEQ + c * CHUNK;
    if (threadIdx.x < CHUNK) as_[threadIdx.x] = g_a[m0 + threadIdx.x];
    __syncthreads();

    const float* bp = g_B  + (size_t)m0 * DI + d;
    const float* xp = g_xi + (size_t)m0 * DI + d;
    float h = 0.f;
#pragma unroll 4
    for (int t = 0; t < CHUNK; t++)
        h = fmaf(as_[t], h, bp[(size_t)t * DI] * xp[(size_t)t * DI]);

    g_Hend[((size_t)(b * NCH + c)) * DI + d] = h;
    if (blockIdx.x == 0 && threadIdx.x == 0) {
        float ap = 1.f;
#pragma unroll
        for (int t = 0; t < CHUNK; t++) ap *= as_[t];
        g_Aprod[b * NCH + c] = ap;
    }
}

__global__ __launch_bounds__(256)
void scan_carry_kernel()
{
    const int idx = blockIdx.x * blockDim.x + threadIdx.x;
    const int b = idx / DI, d = idx % DI;
    float carry = 0.f;
#pragma unroll
    for (int c = 0; c < NCH; c++) {
        size_t o = ((size_t)(b * NCH + c)) * DI + d;
        g_Hcarry[o] = carry;
        carry = fmaf(g_Aprod[b * NCH + c], carry, g_Hend[o]);
    }
}

__global__ __launch_bounds__(256)
void scan_final_kernel(const float* __restrict__ Dvec)
{
    __shared__ float as_[CHUNK];
    const int d = blockIdx.x * blockDim.x + threadIdx.x;
    const int c = blockIdx.y, b = blockIdx.z;
    const int m0 = b * SEQ + c * CHUNK;
    if (threadIdx.x < CHUNK) as_[threadIdx.x] = g_a[m0 + threadIdx.x];
    __syncthreads();

    const float* bp  = g_B  + (size_t)m0 * DI + d;
    const float* xp  = g_xi + (size_t)m0 * DI + d;
    const float* cp  = g_C  + (size_t)m0 * DI + d;
    const float* szp = g_sz + (size_t)m0 * DI + d;
    float*       yp  = g_y  + (size_t)m0 * DI + d;

    const float Dd = Dvec[d];
    float h = g_Hcarry[((size_t)(b * NCH + c)) * DI + d];
#pragma unroll 4
    for (int t = 0; t < CHUNK; t++) {
        float xv = xp[(size_t)t * DI];
        h = fmaf(as_[t], h, bp[(size_t)t * DI] * xv);
        float yv = fmaf(cp[(size_t)t * DI], h, Dd * xv);
        yp[(size_t)t * DI] = yv * szp[(size_t)t * DI];
    }
}

// --------------------------------- launch ----------------------------------
extern "C" void kernel_launch(void* const* d_in, const int* in_sizes, int n_in,
                              void* d_out, int out_size)
{
    const float* x     = (const float*)d_in[0];
    const float* W_in  = (const float*)d_in[1];
    const float* W_xp  = (const float*)d_in[2];
    const float* W_B   = (const float*)d_in[3];
    const float* W_C   = (const float*)d_in[4];
    const float* W_out = (const float*)d_in[5];
    const float* Dvec  = (const float*)d_in[6];
    const float* A_log = (const float*)d_in[7];
    float* out = (float*)d_out;

    // 0) weight transpose + hi/lo split
    k_wsplit_in <<<dim3((2 * DI) / 32, DM / 32), dim3(32, 8)>>>(W_in);
    k_wsplit_out<<<dim3(DM / 32, DI / 32),      dim3(32, 8)>>>(W_out);
    k_wsplit_xp <<<(PN * DI + 255) / 256, 256>>>(W_xp);
    // 1) xz = x @ W_in -> xi, silu(z)   [mma.sync bf16 split]
    k_mma_in<<<dim3((2 * DI) / 64, MTOK / 128), 256>>>(x);
    // 2) proj = xi @ W_xp -> a, B_raw, C_raw   [mma.sync bf16 split]
    k_proj_mma<<<MTOK / 128, 256>>>(A_log);
    // 3) B = B_raw @ W_B ; C = C_raw @ W_C
    k_gemm_bc<<<dim3(DI / BN, MTOK / BM, 2), 256>>>(W_B, W_C);
    // 4) chunked scan + gating -> y
    scan_chunk_kernel<<<dim3(DI / 256, NCH, BATCH), 256>>>();
    scan_carry_kernel<<<(BATCH * DI) / 256, 256>>>();
    scan_final_kernel<<<dim3(DI / 256, NCH, BATCH), 256>>>(Dvec);
    // 5) out = y @ W_out   [mma.sync bf16 split]
    k_mma_out<<<dim3(DM / 64, MTOK / 128), 256>>>(out);
}

// round 13
// speedup vs baseline: 3.6255x; 1.2495x over previous
#include <cuda_runtime.h>
#include <cuda_bf16.h>
#include <math.h>
#include <stdint.h>

// ---------------------------------------------------------------------------
// MambaSSD — split-bf16 mma.sync everywhere; activations pre-split to bf16
// hi/lo in HBM so GEMM inner loops are pure uint4 smem copies.
// out = ((C*h + D*xi) * silu(z)) @ W_out
// ---------------------------------------------------------------------------

#define BATCH 4
#define SEQ   2048
#define DM    1024
#define DI    2048
#define DS    64
#define MTOK  (BATCH * SEQ)   // 8192
#define NCH   16
#define CHUNK 128

// ------------------------- scratch (device globals) ------------------------
__device__ float g_xi[MTOK * DI];
__device__ float g_sz[MTOK * DI];
__device__ float g_a[MTOK];
__device__ float g_Braw[MTOK * DS];
__device__ float g_Craw[MTOK * DS];
__device__ float g_B[MTOK * DI];
__device__ float g_C[MTOK * DI];
__device__ float g_Hend[BATCH * NCH * DI];
__device__ float g_Hcarry[BATCH * NCH * DI];
__device__ float g_Aprod[BATCH * NCH];
// activations split to bf16 hi/lo
__device__ __nv_bfloat16 g_xh[MTOK * DM];        // x hi/lo  [8192,1024]
__device__ __nv_bfloat16 g_xl[MTOK * DM];
__device__ __nv_bfloat16 g_yh[MTOK * DI];        // y hi/lo  [8192,2048]
__device__ __nv_bfloat16 g_yl[MTOK * DI];
// transposed + split weights: [N, K] bf16 hi/lo
__device__ __nv_bfloat16 g_Wih[(2 * DI) * DM];   // W_in^T  [4096,1024]
__device__ __nv_bfloat16 g_Wil[(2 * DI) * DM];
__device__ __nv_bfloat16 g_Woh[DM * DI];         // W_out^T [1024,2048]
__device__ __nv_bfloat16 g_Wol[DM * DI];
#define PN 144                                    // padded N for proj (129->144)
__device__ __nv_bfloat16 g_Wxh[PN * DI];         // W_xp^T  [144,2048] (pad=0)
__device__ __nv_bfloat16 g_Wxl[PN * DI];

// ------------------------------ PTX helpers --------------------------------
__device__ __forceinline__ uint32_t smem_u32(const void* p) {
    uint32_t a;
    asm("{ .reg .u64 t; cvta.to.shared.u64 t, %1; cvt.u32.u64 %0, t; }"
        : "=r"(a) : "l"(p));
    return a;
}

__device__ __forceinline__ void mma16816(float* d, const uint32_t* a, const uint32_t* b) {
    asm volatile(
        "mma.sync.aligned.m16n8k16.row.col.f32.bf16.bf16.f32 "
        "{%0,%1,%2,%3}, {%4,%5,%6,%7}, {%8,%9}, {%0,%1,%2,%3};"
        : "+f"(d[0]), "+f"(d[1]), "+f"(d[2]), "+f"(d[3])
        : "r"(a[0]), "r"(a[1]), "r"(a[2]), "r"(a[3]), "r"(b[0]), "r"(b[1]));
}

__device__ __forceinline__ void ldsm4(uint32_t* r, uint32_t addr) {
    asm volatile("ldmatrix.sync.aligned.m8n8.x4.shared.b16 {%0,%1,%2,%3}, [%4];"
                 : "=r"(r[0]), "=r"(r[1]), "=r"(r[2]), "=r"(r[3]) : "r"(addr));
}
__device__ __forceinline__ void ldsm2(uint32_t* r, uint32_t addr) {
    asm volatile("ldmatrix.sync.aligned.m8n8.x2.shared.b16 {%0,%1}, [%2];"
                 : "=r"(r[0]), "=r"(r[1]) : "r"(addr));
}

__device__ __forceinline__ uint32_t pack_bf2(float a, float b) {
    __nv_bfloat162 t = __floats2bfloat162_rn(a, b);
    return *(uint32_t*)&t;
}

#define KPAD 40   // smem row stride in bf16 (80B = 5*16B): conflict-free ldmatrix

// --------------- mma.sync split-bf16 GEMM, 128x128 CTA tile ----------------
// C[M,N] = A[M,K] @ Bt[N,K]^T, A/B given as bf16 hi/lo in gmem.
// BK=32; 8 warps: 4M x 2N, warp tile 32x64 (2 m16 x 8 n8).
// EPI 0: store fp32 to Cout.  EPI 1: xi (cols<DI) / silu -> g_sz.
template<int EPI>
__device__ void mma_gemm2_dev(const __nv_bfloat16* __restrict__ Ahi,
                              const __nv_bfloat16* __restrict__ Alo,
                              const __nv_bfloat16* __restrict__ Bhi,
                              const __nv_bfloat16* __restrict__ Blo,
                              float* __restrict__ Cout, int N, int K)
{
    __shared__ __align__(16) __nv_bfloat16 sAh[128 * KPAD];
    __shared__ __align__(16) __nv_bfloat16 sAl[128 * KPAD];
    __shared__ __align__(16) __nv_bfloat16 sBh[128 * KPAD];
    __shared__ __align__(16) __nv_bfloat16 sBl[128 * KPAD];

    const int tid  = threadIdx.x;
    const int wid  = tid >> 5;
    const int lane = tid & 31;
    const int warpM = wid >> 1;       // 0..3
    const int warpN = wid & 1;        // 0..1
    const int rowBase = blockIdx.y * 128;
    const int colBase = blockIdx.x * 128;
    const int NC = K / 32;

    const uint32_t ahB = smem_u32(sAh);
    const uint32_t alB = smem_u32(sAl);
    const uint32_t bhB = smem_u32(sBh);
    const uint32_t blB = smem_u32(sBl);

    float acc[2][8][4];
#pragma unroll
    for (int i = 0; i < 2; i++)
#pragma unroll
        for (int j = 0; j < 8; j++)
#pragma unroll
            for (int q = 0; q < 4; q++) acc[i][j][q] = 0.f;

    for (int c = 0; c < NC; ++c) {
        __syncthreads();
        // 512 uint4 slots per array; each thread copies 2 slots per array
#pragma unroll
        for (int s = tid; s < 512; s += 256) {
            const int row = s >> 2, q = s & 3;
            const int so = row * KPAD + q * 8;
            const size_t ga = (size_t)(rowBase + row) * K + c * 32 + q * 8;
            const size_t gb = (size_t)(colBase + row) * K + c * 32 + q * 8;
            *(uint4*)(sAh + so) = *(const uint4*)(Ahi + ga);
            *(uint4*)(sAl + so) = *(const uint4*)(Alo + ga);
            *(uint4*)(sBh + so) = *(const uint4*)(Bhi + gb);
            *(uint4*)(sBl + so) = *(const uint4*)(Blo + gb);
        }
        __syncthreads();

#pragma unroll
        for (int ks = 0; ks < 2; ks++) {
            const int k0 = ks * 16;
            uint32_t ah[2][4], al[2][4];
#pragma unroll
            for (int mi = 0; mi < 2; mi++) {
                const int m0 = warpM * 32 + mi * 16;
                const uint32_t off =
                    (uint32_t)(((m0 + (lane & 15)) * KPAD + k0 + (lane >> 4) * 8) * 2);
                ldsm4(ah[mi], ahB + off);
                ldsm4(al[mi], alB + off);
            }
#pragma unroll
            for (int njp = 0; njp < 4; njp++) {
                const int n0 = warpN * 64 + njp * 16;
                // x4: lanes0-7 tile0 k-lo, 8-15 tile0 k-hi, 16-23 tile1 k-lo, 24-31 tile1 k-hi
                const uint32_t off = (uint32_t)(((n0 + (lane & 7) + ((lane >> 4) & 1) * 8)
                                     * KPAD + k0 + ((lane >> 3) & 1) * 8) * 2);
                uint32_t bh[4], bl[4];
                ldsm4(bh, bhB + off);
                ldsm4(bl, blB + off);
#pragma unroll
                for (int mi = 0; mi < 2; mi++) {
                    mma16816(acc[mi][njp * 2],     ah[mi], bh);
                    mma16816(acc[mi][njp * 2],     ah[mi], bl);
                    mma16816(acc[mi][njp * 2],     al[mi], bh);
                    mma16816(acc[mi][njp * 2 + 1], ah[mi], bh + 2);
                    mma16816(acc[mi][njp * 2 + 1], ah[mi], bl + 2);
                    mma16816(acc[mi][njp * 2 + 1], al[mi], bh + 2);
                }
            }
        }
    }

    const int qr = lane >> 2, qc = lane & 3;
#pragma unroll
    for (int mi = 0; mi < 2; mi++) {
#pragma unroll
        for (int nj = 0; nj < 8; nj++) {
            const int m0 = rowBase + warpM * 32 + mi * 16;
            const int nn = warpN * 64 + nj * 8 + qc * 2;
            float c0 = acc[mi][nj][0], c1 = acc[mi][nj][1];
            float c2 = acc[mi][nj][2], c3 = acc[mi][nj][3];
            if (EPI == 0) {
                float* p0 = Cout + (size_t)(m0 + qr) * N + colBase + nn;
                float* p1 = Cout + (size_t)(m0 + qr + 8) * N + colBase + nn;
                *(float2*)p0 = make_float2(c0, c1);
                *(float2*)p1 = make_float2(c2, c3);
            } else {
                const bool zside = (colBase >= DI);
                const int cb = (zside ? colBase - DI : colBase) + nn;
                float* base = zside ? g_sz : g_xi;
                if (zside) {
                    c0 = c0 / (1.f + expf(-c0));
                    c1 = c1 / (1.f + expf(-c1));
                    c2 = c2 / (1.f + expf(-c2));
                    c3 = c3 / (1.f + expf(-c3));
                }
                *(float2*)(base + (size_t)(m0 + qr) * DI + cb)     = make_float2(c0, c1);
                *(float2*)(base + (size_t)(m0 + qr + 8) * DI + cb) = make_float2(c2, c3);
            }
        }
    }
}

__global__ __launch_bounds__(256, 2)
void k_mma_in()
{
    mma_gemm2_dev<1>(g_xh, g_xl, g_Wih, g_Wil, nullptr, 2 * DI, DM);
}

__global__ __launch_bounds__(256, 2)
void k_mma_out(float* __restrict__ out)
{
    mma_gemm2_dev<0>(g_yh, g_yl, g_Woh, g_Wol, out, DM, DI);
}

// -------------------- activation split: x -> g_xh/g_xl ---------------------
__global__ __launch_bounds__(256)
void k_split_x(const float* __restrict__ x)
{
    const int idx4 = blockIdx.x * 256 + threadIdx.x;   // 4 floats per thread
    const size_t base = (size_t)idx4 * 4;
    float4 v = *(const float4*)(x + base);
    float f[4] = {v.x, v.y, v.z, v.w};
    __nv_bfloat16 h[4];
    uint32_t hp[2], lp[2];
    float lf[4];
#pragma unroll
    for (int j = 0; j < 4; j++) {
        h[j] = __float2bfloat16(f[j]);
        lf[j] = f[j] - __bfloat162float(h[j]);
    }
    hp[0] = pack_bf2(__bfloat162float(h[0]), __bfloat162float(h[1]));
    hp[1] = pack_bf2(__bfloat162float(h[2]), __bfloat162float(h[3]));
    lp[0] = pack_bf2(lf[0], lf[1]);
    lp[1] = pack_bf2(lf[2], lf[3]);
    *(uint2*)(g_xh + base) = make_uint2(hp[0], hp[1]);
    *(uint2*)(g_xl + base) = make_uint2(lp[0], lp[1]);
}

// ----------------- proj = xi @ W_xp via mma.sync (N pad 144) ----------------
__device__ __forceinline__ void proj_store(int m, int col, float v, float Aval)
{
    if (col == 0) {
        float dlt = (v > 20.f) ? v : log1pf(expf(v));
        g_a[m] = expf(Aval * dlt);
    } else if (col <= DS) {
        g_Braw[(size_t)m * DS + (col - 1)] = v;
    } else if (col <= 2 * DS) {
        g_Craw[(size_t)m * DS + (col - 1 - DS)] = v;
    }
}

__global__ __launch_bounds__(256, 1)
void k_proj_mma(const float* __restrict__ A_log)
{
    __shared__ __align__(16) __nv_bfloat16 sAh[128 * KPAD];
    __shared__ __align__(16) __nv_bfloat16 sAl[128 * KPAD];
    __shared__ __align__(16) __nv_bfloat16 sBh[PN * KPAD];
    __shared__ __align__(16) __nv_bfloat16 sBl[PN * KPAD];

    const int tid  = threadIdx.x;
    const int wid  = tid >> 5;
    const int lane = tid & 31;
    const int warpM = wid >> 1;
    const int warpN = wid & 1;
    const int rowBase = blockIdx.x * 128;
    const int NC = DI / 32;

    const uint32_t ahB = smem_u32(sAh);
    const uint32_t alB = smem_u32(sAl);
    const uint32_t bhB = smem_u32(sBh);
    const uint32_t blB = smem_u32(sBl);

    float acc[2][9][4];
#pragma unroll
    for (int i = 0; i < 2; i++)
#pragma unroll
        for (int j = 0; j < 9; j++)
#pragma unroll
            for (int q = 0; q < 4; q++) acc[i][j][q] = 0.f;

    const int lr = tid >> 1, lh = tid & 1;

    for (int c = 0; c < NC; ++c) {
        __syncthreads();
        {
            const float* ap = g_xi + (size_t)(rowBase + lr) * DI + c * 32 + lh * 16;
            float4 v0 = *(const float4*)(ap + 0);
            float4 v1 = *(const float4*)(ap + 4);
            float4 v2 = *(const float4*)(ap + 8);
            float4 v3 = *(const float4*)(ap + 12);
            float f[16] = {v0.x,v0.y,v0.z,v0.w, v1.x,v1.y,v1.z,v1.w,
                           v2.x,v2.y,v2.z,v2.w, v3.x,v3.y,v3.z,v3.w};
            float hf[16], lf[16];
#pragma unroll
            for (int j = 0; j < 16; j++) {
                __nv_bfloat16 h = __float2bfloat16(f[j]);
                hf[j] = __bfloat162float(h);
                lf[j] = f[j] - hf[j];
            }
            uint4 h0, h1, l0, l1;
            h0.x = pack_bf2(hf[0], hf[1]);  h0.y = pack_bf2(hf[2], hf[3]);
            h0.z = pack_bf2(hf[4], hf[5]);  h0.w = pack_bf2(hf[6], hf[7]);
            h1.x = pack_bf2(hf[8], hf[9]);  h1.y = pack_bf2(hf[10], hf[11]);
            h1.z = pack_bf2(hf[12], hf[13]);h1.w = pack_bf2(hf[14], hf[15]);
            l0.x = pack_bf2(lf[0], lf[1]);  l0.y = pack_bf2(lf[2], lf[3]);
            l0.z = pack_bf2(lf[4], lf[5]);  l0.w = pack_bf2(lf[6], lf[7]);
            l1.x = pack_bf2(lf[8], lf[9]);  l1.y = pack_bf2(lf[10], lf[11]);
            l1.z = pack_bf2(lf[12], lf[13]);l1.w = pack_bf2(lf[14], lf[15]);
            const int so = lr * KPAD + lh * 16;
            *(uint4*)(sAh + so)     = h0;
            *(uint4*)(sAh + so + 8) = h1;
            *(uint4*)(sAl + so)     = l0;
            *(uint4*)(sAl + so + 8) = l1;
        }
        for (int i = tid; i < PN * 4; i += 256) {
            const int row = i >> 2, q = i & 3;
            const size_t go = (size_t)row * DI + c * 32 + q * 8;
            const int so = row * KPAD + q * 8;
            *(uint4*)(sBh + so) = *(const uint4*)(g_Wxh + go);
            *(uint4*)(sBl + so) = *(const uint4*)(g_Wxl + go);
        }
        __syncthreads();

#pragma unroll
        for (int ks = 0; ks < 2; ks++) {
            const int k0 = ks * 16;
            uint32_t ah[2][4], al[2][4];
#pragma unroll
            for (int mi = 0; mi < 2; mi++) {
                const int m0 = warpM * 32 + mi * 16;
                const uint32_t off =
                    (uint32_t)(((m0 + (lane & 15)) * KPAD + k0 + (lane >> 4) * 8) * 2);
                ldsm4(ah[mi], ahB + off);
                ldsm4(al[mi], alB + off);
            }
#pragma unroll
            for (int nj = 0; nj < 9; nj++) {
                const int n0 = warpN * 72 + nj * 8;
                const uint32_t off =
                    (uint32_t)(((n0 + (lane & 7)) * KPAD + k0 + ((lane >> 3) & 1) * 8) * 2);
                uint32_t bh[2], bl[2];
                ldsm2(bh, bhB + off);
                ldsm2(bl, blB + off);
#pragma unroll
                for (int mi = 0; mi < 2; mi++) {
                    mma16816(acc[mi][nj], ah[mi], bh);
                    mma16816(acc[mi][nj], ah[mi], bl);
                    mma16816(acc[mi][nj], al[mi], bh);
                }
            }
        }
    }

    const float Aval = -expf(*A_log);
    const int qr = lane >> 2, qc = lane & 3;
#pragma unroll
    for (int mi = 0; mi < 2; mi++) {
#pragma unroll
        for (int nj = 0; nj < 9; nj++) {
            const int m0 = rowBase + warpM * 32 + mi * 16;
            const int nn = warpN * 72 + nj * 8 + qc * 2;
            proj_store(m0 + qr,     nn,     acc[mi][nj][0], Aval);
            proj_store(m0 + qr,     nn + 1, acc[mi][nj][1], Aval);
            proj_store(m0 + qr + 8, nn,     acc[mi][nj][2], Aval);
            proj_store(m0 + qr + 8, nn + 1, acc[mi][nj][3], Aval);
        }
    }
}

// -------------------- weight transpose + bf16 hi/lo split -------------------
__device__ void wsplit_dev(const float* __restrict__ W,
                           __nv_bfloat16* __restrict__ Thi,
                           __nv_bfloat16* __restrict__ Tlo, int K, int N)
{
    __shared__ float ts[32][33];
    const int n0 = blockIdx.x * 32, k0 = blockIdx.y * 32;
    const int tx = threadIdx.x, ty = threadIdx.y;
    for (int i = ty; i < 32; i += 8)
        ts[i][tx] = W[(size_t)(k0 + i) * N + n0 + tx];
    __syncthreads();
    for (int i = ty; i < 32; i += 8) {
        float v = ts[tx][i];
        __nv_bfloat16 h = __float2bfloat16(v);
        float lf = v - __bfloat162float(h);
        size_t o = (size_t)(n0 + i) * K + k0 + tx;
        Thi[o] = h;
        Tlo[o] = __float2bfloat16(lf);
    }
}

__global__ __launch_bounds__(256)
void k_wsplit_in(const float* __restrict__ W) { wsplit_dev(W, g_Wih, g_Wil, DM, 2 * DI); }
__global__ __launch_bounds__(256)
void k_wsplit_out(const float* __restrict__ W) { wsplit_dev(W, g_Woh, g_Wol, DI, DM); }

__global__ __launch_bounds__(256)
void k_wsplit_xp(const float* __restrict__ Wxp)
{
    const int idx = blockIdx.x * 256 + threadIdx.x;
    if (idx >= PN * DI) return;
    const int n = idx / DI, k = idx % DI;
    float v = (n < 129) ? Wxp[(size_t)k * 129 + n] : 0.f;
    __nv_bfloat16 h = __float2bfloat16(v);
    float lf = v - __bfloat162float(h);
    g_Wxh[idx] = h;
    g_Wxl[idx] = __float2bfloat16(lf);
}

// ------------------------ SIMT SGEMM (B/C expansion) ------------------------
#define BM 128
#define BN 128
#define BKK 8
__device__ __forceinline__
void sgemm_dev(const float* __restrict__ A, const float* __restrict__ B,
               float* __restrict__ C0, int N, int K)
{
    __shared__ float As[BKK][BM];
    __shared__ float Bs[BKK][BN];
    const int tid = threadIdx.x;
    const int rowBase = blockIdx.y * BM;
    const int colBase = blockIdx.x * BN;
    const int aRow = tid >> 1, aK = (tid & 1) * 4;
    const int bK = tid >> 5, bCol = (tid & 31) * 4;
    const float* Aptr = A + (size_t)(rowBase + aRow) * K + aK;
    const float* Bptr = B + (size_t)bK * N + colBase + bCol;
    const int ty = tid >> 4, tx = tid & 15;

    float acc[8][8];
#pragma unroll
    for (int i = 0; i < 8; i++)
#pragma unroll
        for (int j = 0; j < 8; j++) acc[i][j] = 0.f;

    for (int k0 = 0; k0 < K; k0 += BKK) {
        float4 av = *(const float4*)(Aptr + k0);
        float4 bv = *(const float4*)(Bptr + (size_t)k0 * N);
        __syncthreads();
        As[aK + 0][aRow] = av.x; As[aK + 1][aRow] = av.y;
        As[aK + 2][aRow] = av.z; As[aK + 3][aRow] = av.w;
        *(float4*)&Bs[bK][bCol] = bv;
        __syncthreads();
#pragma unroll
        for (int kk = 0; kk < BKK; kk++) {
            float4 a0 = *(const float4*)(&As[kk][ty * 8]);
            float4 a1 = *(const float4*)(&As[kk][ty * 8 + 4]);
            float4 b0 = *(const float4*)(&Bs[kk][tx * 8]);
            float4 b1 = *(const float4*)(&Bs[kk][tx * 8 + 4]);
            float ar[8] = {a0.x, a0.y, a0.z, a0.w, a1.x, a1.y, a1.z, a1.w};
            float br[8] = {b0.x, b0.y, b0.z, b0.w, b1.x, b1.y, b1.z, b1.w};
#pragma unroll
            for (int i = 0; i < 8; i++)
#pragma unroll
                for (int j = 0; j < 8; j++)
                    acc[i][j] = fmaf(ar[i], br[j], acc[i][j]);
        }
    }
#pragma unroll
    for (int i = 0; i < 8; i++) {
        int row = rowBase + ty * 8 + i;
        float* cp = C0 + (size_t)row * N + colBase + tx * 8;
        *(float4*)cp       = make_float4(acc[i][0], acc[i][1], acc[i][2], acc[i][3]);
        *(float4*)(cp + 4) = make_float4(acc[i][4], acc[i][5], acc[i][6], acc[i][7]);
    }
}

__global__ __launch_bounds__(256)
void k_gemm_bc(const float* __restrict__ W_B, const float* __restrict__ W_C)
{
    if (blockIdx.z == 0) sgemm_dev(g_Braw, W_B, g_B, DI, DS);
    else                 sgemm_dev(g_Craw, W_C, g_C, DI, DS);
}

// ------------------------------- 3-phase scan ------------------------------
__global__ __launch_bounds__(256)
void scan_chunk_kernel()
{
    __shared__ float as_[CHUNK];
    const int d = blockIdx.x * blockDim.x + threadIdx.x;
    const int c = blockIdx.y, b = blockIdx.z;
    const int m0 = b * SEQ + c * CHUNK;
    if (threadIdx.x < CHUNK) as_[threadIdx.x] = g_a[m0 + threadIdx.x];
    __syncthreads();

    const float* bp = g_B  + (size_t)m0 * DI + d;
    const float* xp = g_xi + (size_t)m0 * DI + d;
    float h = 0.f;
#pragma unroll 4
    for (int t = 0; t < CHUNK; t++)
        h = fmaf(as_[t], h, bp[(size_t)t * DI] * xp[(size_t)t * DI]);

    g_Hend[((size_t)(b * NCH + c)) * DI + d] = h;
    if (blockIdx.x == 0 && threadIdx.x == 0) {
        float ap = 1.f;
#pragma unroll
        for (int t = 0; t < CHUNK; t++) ap *= as_[t];
        g_Aprod[b * NCH + c] = ap;
    }
}

__global__ __launch_bounds__(256)
void scan_carry_kernel()
{
    const int idx = blockIdx.x * blockDim.x + threadIdx.x;
    const int b = idx / DI, d = idx % DI;
    float carry = 0.f;
#pragma unroll
    for (int c = 0; c < NCH; c++) {
        size_t o = ((size_t)(b * NCH + c)) * DI + d;
        g_Hcarry[o] = carry;
        carry = fmaf(g_Aprod[b * NCH + c], carry, g_Hend[o]);
    }
}

__global__ __launch_bounds__(256)
void scan_final_kernel(const float* __restrict__ Dvec)
{
    __shared__ float as_[CHUNK];
    const int d = blockIdx.x * blockDim.x + threadIdx.x;
    const int c = blockIdx.y, b = blockIdx.z;
    const int m0 = b * SEQ + c * CHUNK;
    if (threadIdx.x < CHUNK) as_[threadIdx.x] = g_a[m0 + threadIdx.x];
    __syncthreads();

    const float* bp  = g_B  + (size_t)m0 * DI + d;
    const float* xp  = g_xi + (size_t)m0 * DI + d;
    const float* cp  = g_C  + (size_t)m0 * DI + d;
    const float* szp = g_sz + (size_t)m0 * DI + d;
    __nv_bfloat16* yhp = g_yh + (size_t)m0 * DI + d;
    __nv_bfloat16* ylp = g_yl + (size_t)m0 * DI + d;

    const float Dd = Dvec[d];
    float h = g_Hcarry[((size_t)(b * NCH + c)) * DI + d];
#pragma unroll 4
    for (int t = 0; t < CHUNK; t++) {
        float xv = xp[(size_t)t * DI];
        h = fmaf(as_[t], h, bp[(size_t)t * DI] * xv);
        float yv = fmaf(cp[(size_t)t * DI], h, Dd * xv);
        yv *= szp[(size_t)t * DI];
        __nv_bfloat16 yh = __float2bfloat16(yv);
        float yl = yv - __bfloat162float(yh);
        yhp[(size_t)t * DI] = yh;
        ylp[(size_t)t * DI] = __float2bfloat16(yl);
    }
}

// --------------------------------- launch ----------------------------------
extern "C" void kernel_launch(void* const* d_in, const int* in_sizes, int n_in,
                              void* d_out, int out_size)
{
    const float* x     = (const float*)d_in[0];
    const float* W_in  = (const float*)d_in[1];
    const float* W_xp  = (const float*)d_in[2];
    const float* W_B   = (const float*)d_in[3];
    const float* W_C   = (const float*)d_in[4];
    const float* W_out = (const float*)d_in[5];
    const float* Dvec  = (const float*)d_in[6];
    const float* A_log = (const float*)d_in[7];
    float* out = (float*)d_out;

    // 0) weight + activation splits
    k_wsplit_in <<<dim3((2 * DI) / 32, DM / 32), dim3(32, 8)>>>(W_in);
    k_wsplit_out<<<dim3(DM / 32, DI / 32),      dim3(32, 8)>>>(W_out);
    k_wsplit_xp <<<(PN * DI + 255) / 256, 256>>>(W_xp);
    k_split_x   <<<(MTOK * DM / 4) / 256, 256>>>(x);
    // 1) xz = x @ W_in -> xi, silu(z)   [mma.sync, 128x128 tiles]
    k_mma_in<<<dim3((2 * DI) / 128, MTOK / 128), 256>>>();
    // 2) proj = xi @ W_xp -> a, B_raw, C_raw
    k_proj_mma<<<MTOK / 128, 256>>>(A_log);
    // 3) B = B_raw @ W_B ; C = C_raw @ W_C
    k_gemm_bc<<<dim3(DI / BN, MTOK / BM, 2), 256>>>(W_B, W_C);
    // 4) chunked scan + gating -> y (split bf16)
    scan_chunk_kernel<<<dim3(DI / 256, NCH, BATCH), 256>>>();
    scan_carry_kernel<<<(BATCH * DI) / 256, 256>>>();
    scan_final_kernel<<<dim3(DI / 256, NCH, BATCH), 256>>>(Dvec);
    // 5) out = y @ W_out   [mma.sync, 128x128 tiles]
    k_mma_out<<<dim3(DM / 128, MTOK / 128), 256>>>(out);
}

// round 14
// speedup vs baseline: 3.8875x; 1.0722x over previous
#include <cuda_runtime.h>
#include <cuda_bf16.h>
#include <math.h>
#include <stdint.h>

// ---------------------------------------------------------------------------
// MambaSSD — split-bf16 mma.sync for all GEMMs (in, proj, B/C expansion, out).
// Activations pre-split to bf16 hi/lo in HBM; cp.async smem fills.
// out = ((C*h + D*xi) * silu(z)) @ W_out
// ---------------------------------------------------------------------------

#define BATCH 4
#define SEQ   2048
#define DM    1024
#define DI    2048
#define DS    64
#define MTOK  (BATCH * SEQ)   // 8192
#define NCH   16
#define CHUNK 128

// ------------------------- scratch (device globals) ------------------------
__device__ float g_xi[MTOK * DI];
__device__ float g_sz[MTOK * DI];
__device__ float g_a[MTOK];
__device__ float g_B[MTOK * DI];
__device__ float g_C[MTOK * DI];
__device__ float g_Hend[BATCH * NCH * DI];
__device__ float g_Hcarry[BATCH * NCH * DI];
__device__ float g_Aprod[BATCH * NCH];
// activations split to bf16 hi/lo
__device__ __nv_bfloat16 g_xh[MTOK * DM];
__device__ __nv_bfloat16 g_xl[MTOK * DM];
__device__ __nv_bfloat16 g_yh[MTOK * DI];
__device__ __nv_bfloat16 g_yl[MTOK * DI];
__device__ __nv_bfloat16 g_Brh[MTOK * DS];       // Braw hi/lo
__device__ __nv_bfloat16 g_Brl[MTOK * DS];
__device__ __nv_bfloat16 g_Crh[MTOK * DS];
__device__ __nv_bfloat16 g_Crl[MTOK * DS];
// transposed + split weights: [N, K] bf16 hi/lo
__device__ __nv_bfloat16 g_Wih[(2 * DI) * DM];
__device__ __nv_bfloat16 g_Wil[(2 * DI) * DM];
__device__ __nv_bfloat16 g_Woh[DM * DI];
__device__ __nv_bfloat16 g_Wol[DM * DI];
__device__ __nv_bfloat16 g_WBh[DI * DS];         // W_B^T [2048,64]
__device__ __nv_bfloat16 g_WBl[DI * DS];
__device__ __nv_bfloat16 g_WCh[DI * DS];
__device__ __nv_bfloat16 g_WCl[DI * DS];
#define PN 144
__device__ __nv_bfloat16 g_Wxh[PN * DI];
__device__ __nv_bfloat16 g_Wxl[PN * DI];

// ------------------------------ PTX helpers --------------------------------
__device__ __forceinline__ uint32_t smem_u32(const void* p) {
    uint32_t a;
    asm("{ .reg .u64 t; cvta.to.shared.u64 t, %1; cvt.u32.u64 %0, t; }"
        : "=r"(a) : "l"(p));
    return a;
}

__device__ __forceinline__ void mma16816(float* d, const uint32_t* a, const uint32_t* b) {
    asm volatile(
        "mma.sync.aligned.m16n8k16.row.col.f32.bf16.bf16.f32 "
        "{%0,%1,%2,%3}, {%4,%5,%6,%7}, {%8,%9}, {%0,%1,%2,%3};"
        : "+f"(d[0]), "+f"(d[1]), "+f"(d[2]), "+f"(d[3])
        : "r"(a[0]), "r"(a[1]), "r"(a[2]), "r"(a[3]), "r"(b[0]), "r"(b[1]));
}

__device__ __forceinline__ void ldsm4(uint32_t* r, uint32_t addr) {
    asm volatile("ldmatrix.sync.aligned.m8n8.x4.shared.b16 {%0,%1,%2,%3}, [%4];"
                 : "=r"(r[0]), "=r"(r[1]), "=r"(r[2]), "=r"(r[3]) : "r"(addr));
}
__device__ __forceinline__ void ldsm2(uint32_t* r, uint32_t addr) {
    asm volatile("ldmatrix.sync.aligned.m8n8.x2.shared.b16 {%0,%1}, [%2];"
                 : "=r"(r[0]), "=r"(r[1]) : "r"(addr));
}

__device__ __forceinline__ void cp16(uint32_t saddr, const void* g) {
    asm volatile("cp.async.cg.shared.global [%0], [%1], 16;"
                 :: "r"(saddr), "l"(g) : "memory");
}
#define CP_WAIT_ALL() asm volatile("cp.async.commit_group;\n\tcp.async.wait_group 0;" ::: "memory")

__device__ __forceinline__ uint32_t pack_bf2(float a, float b) {
    __nv_bfloat162 t = __floats2bfloat162_rn(a, b);
    return *(uint32_t*)&t;
}

#define KPAD 40   // smem row stride in bf16 (80B = 5*16B): conflict-free ldmatrix

// --------------- mma.sync split-bf16 GEMM, 128x128 CTA tile ----------------
// C[M,N] = A[M,K] @ Bt[N,K]^T, A/B given as bf16 hi/lo in gmem.
// BK=32; 8 warps: 4M x 2N, warp tile 32x64.
// EPI 0: fp32 -> Cout.  EPI 1: xi / silu->g_sz split.
template<int EPI>
__device__ void mma_gemm2_dev(const __nv_bfloat16* __restrict__ Ahi,
                              const __nv_bfloat16* __restrict__ Alo,
                              const __nv_bfloat16* __restrict__ Bhi,
                              const __nv_bfloat16* __restrict__ Blo,
                              float* __restrict__ Cout, int N, int K)
{
    __shared__ __align__(16) __nv_bfloat16 sAh[128 * KPAD];
    __shared__ __align__(16) __nv_bfloat16 sAl[128 * KPAD];
    __shared__ __align__(16) __nv_bfloat16 sBh[128 * KPAD];
    __shared__ __align__(16) __nv_bfloat16 sBl[128 * KPAD];

    const int tid  = threadIdx.x;
    const int wid  = tid >> 5;
    const int lane = tid & 31;
    const int warpM = wid >> 1;
    const int warpN = wid & 1;
    const int rowBase = blockIdx.y * 128;
    const int colBase = blockIdx.x * 128;
    const int NC = K / 32;

    const uint32_t ahB = smem_u32(sAh);
    const uint32_t alB = smem_u32(sAl);
    const uint32_t bhB = smem_u32(sBh);
    const uint32_t blB = smem_u32(sBl);

    float acc[2][8][4];
#pragma unroll
    for (int i = 0; i < 2; i++)
#pragma unroll
        for (int j = 0; j < 8; j++)
#pragma unroll
            for (int q = 0; q < 4; q++) acc[i][j][q] = 0.f;

    for (int c = 0; c < NC; ++c) {
        __syncthreads();
#pragma unroll
        for (int s = tid; s < 512; s += 256) {
            const int row = s >> 2, q = s & 3;
            const uint32_t so = (uint32_t)(row * KPAD + q * 8) * 2;
            const size_t ga = (size_t)(rowBase + row) * K + c * 32 + q * 8;
            const size_t gb = (size_t)(colBase + row) * K + c * 32 + q * 8;
            cp16(ahB + so, Ahi + ga);
            cp16(alB + so, Alo + ga);
            cp16(bhB + so, Bhi + gb);
            cp16(blB + so, Blo + gb);
        }
        CP_WAIT_ALL();
        __syncthreads();

#pragma unroll
        for (int ks = 0; ks < 2; ks++) {
            const int k0 = ks * 16;
            uint32_t ah[2][4], al[2][4];
#pragma unroll
            for (int mi = 0; mi < 2; mi++) {
                const int m0 = warpM * 32 + mi * 16;
                const uint32_t off =
                    (uint32_t)(((m0 + (lane & 15)) * KPAD + k0 + (lane >> 4) * 8) * 2);
                ldsm4(ah[mi], ahB + off);
                ldsm4(al[mi], alB + off);
            }
#pragma unroll
            for (int njp = 0; njp < 4; njp++) {
                const int n0 = warpN * 64 + njp * 16;
                const uint32_t off = (uint32_t)(((n0 + (lane & 7) + ((lane >> 4) & 1) * 8)
                                     * KPAD + k0 + ((lane >> 3) & 1) * 8) * 2);
                uint32_t bh[4], bl[4];
                ldsm4(bh, bhB + off);
                ldsm4(bl, blB + off);
#pragma unroll
                for (int mi = 0; mi < 2; mi++) {
                    mma16816(acc[mi][njp * 2],     ah[mi], bh);
                    mma16816(acc[mi][njp * 2],     ah[mi], bl);
                    mma16816(acc[mi][njp * 2],     al[mi], bh);
                    mma16816(acc[mi][njp * 2 + 1], ah[mi], bh + 2);
                    mma16816(acc[mi][njp * 2 + 1], ah[mi], bl + 2);
                    mma16816(acc[mi][njp * 2 + 1], al[mi], bh + 2);
                }
            }
        }
    }

    const int qr = lane >> 2, qc = lane & 3;
#pragma unroll
    for (int mi = 0; mi < 2; mi++) {
#pragma unroll
        for (int nj = 0; nj < 8; nj++) {
            const int m0 = rowBase + warpM * 32 + mi * 16;
            const int nn = warpN * 64 + nj * 8 + qc * 2;
            float c0 = acc[mi][nj][0], c1 = acc[mi][nj][1];
            float c2 = acc[mi][nj][2], c3 = acc[mi][nj][3];
            if (EPI == 0) {
                float* p0 = Cout + (size_t)(m0 + qr) * N + colBase + nn;
                float* p1 = Cout + (size_t)(m0 + qr + 8) * N + colBase + nn;
                *(float2*)p0 = make_float2(c0, c1);
                *(float2*)p1 = make_float2(c2, c3);
            } else {
                const bool zside = (colBase >= DI);
                const int cb = (zside ? colBase - DI : colBase) + nn;
                float* base = zside ? g_sz : g_xi;
                if (zside) {
                    c0 = c0 / (1.f + expf(-c0));
                    c1 = c1 / (1.f + expf(-c1));
                    c2 = c2 / (1.f + expf(-c2));
                    c3 = c3 / (1.f + expf(-c3));
                }
                *(float2*)(base + (size_t)(m0 + qr) * DI + cb)     = make_float2(c0, c1);
                *(float2*)(base + (size_t)(m0 + qr + 8) * DI + cb) = make_float2(c2, c3);
            }
        }
    }
}

__global__ __launch_bounds__(256, 2)
void k_mma_in()
{
    mma_gemm2_dev<1>(g_xh, g_xl, g_Wih, g_Wil, nullptr, 2 * DI, DM);
}

__global__ __launch_bounds__(256, 2)
void k_mma_out(float* __restrict__ out)
{
    mma_gemm2_dev<0>(g_yh, g_yl, g_Woh, g_Wol, out, DM, DI);
}

// B = Braw @ W_B ; C = Craw @ W_C   (K=64, mma path, z selects)
__global__ __launch_bounds__(256, 2)
void k_mma_bc()
{
    if (blockIdx.z == 0)
        mma_gemm2_dev<0>(g_Brh, g_Brl, g_WBh, g_WBl, g_B, DI, DS);
    else
        mma_gemm2_dev<0>(g_Crh, g_Crl, g_WCh, g_WCl, g_C, DI, DS);
}

// -------------------- activation split: x -> g_xh/g_xl ---------------------
__global__ __launch_bounds__(256)
void k_split_x(const float* __restrict__ x)
{
    const int idx4 = blockIdx.x * 256 + threadIdx.x;
    const size_t base = (size_t)idx4 * 4;
    float4 v = *(const float4*)(x + base);
    float f[4] = {v.x, v.y, v.z, v.w};
    float lf[4];
    __nv_bfloat16 h[4];
#pragma unroll
    for (int j = 0; j < 4; j++) {
        h[j] = __float2bfloat16(f[j]);
        lf[j] = f[j] - __bfloat162float(h[j]);
    }
    uint32_t hp0 = pack_bf2(__bfloat162float(h[0]), __bfloat162float(h[1]));
    uint32_t hp1 = pack_bf2(__bfloat162float(h[2]), __bfloat162float(h[3]));
    uint32_t lp0 = pack_bf2(lf[0], lf[1]);
    uint32_t lp1 = pack_bf2(lf[2], lf[3]);
    *(uint2*)(g_xh + base) = make_uint2(hp0, hp1);
    *(uint2*)(g_xl + base) = make_uint2(lp0, lp1);
}

// ----------------- proj = xi @ W_xp via mma.sync (N pad 144) ----------------
// Epilogue: col0 -> a; 1..64 -> Braw hi/lo; 65..128 -> Craw hi/lo.
__device__ __forceinline__ void proj_store(int m, int col, float v, float Aval)
{
    if (col == 0) {
        float dlt = (v > 20.f) ? v : log1pf(expf(v));
        g_a[m] = expf(Aval * dlt);
    } else if (col <= 2 * DS) {
        __nv_bfloat16 h = __float2bfloat16(v);
        __nv_bfloat16 l = __float2bfloat16(v - __bfloat162float(h));
        if (col <= DS) {
            g_Brh[(size_t)m * DS + (col - 1)] = h;
            g_Brl[(size_t)m * DS + (col - 1)] = l;
        } else {
            g_Crh[(size_t)m * DS + (col - 1 - DS)] = h;
            g_Crl[(size_t)m * DS + (col - 1 - DS)] = l;
        }
    }
}

__global__ __launch_bounds__(256, 1)
void k_proj_mma(const float* __restrict__ A_log)
{
    __shared__ __align__(16) __nv_bfloat16 sAh[128 * KPAD];
    __shared__ __align__(16) __nv_bfloat16 sAl[128 * KPAD];
    __shared__ __align__(16) __nv_bfloat16 sBh[PN * KPAD];
    __shared__ __align__(16) __nv_bfloat16 sBl[PN * KPAD];

    const int tid  = threadIdx.x;
    const int wid  = tid >> 5;
    const int lane = tid & 31;
    const int warpM = wid >> 1;
    const int warpN = wid & 1;
    const int rowBase = blockIdx.x * 128;
    const int NC = DI / 32;

    const uint32_t ahB = smem_u32(sAh);
    const uint32_t alB = smem_u32(sAl);
    const uint32_t bhB = smem_u32(sBh);
    const uint32_t blB = smem_u32(sBl);

    float acc[2][9][4];
#pragma unroll
    for (int i = 0; i < 2; i++)
#pragma unroll
        for (int j = 0; j < 9; j++)
#pragma unroll
            for (int q = 0; q < 4; q++) acc[i][j][q] = 0.f;

    const int lr = tid >> 1, lh = tid & 1;

    for (int c = 0; c < NC; ++c) {
        __syncthreads();
        {
            const float* ap = g_xi + (size_t)(rowBase + lr) * DI + c * 32 + lh * 16;
            float4 v0 = *(const float4*)(ap + 0);
            float4 v1 = *(const float4*)(ap + 4);
            float4 v2 = *(const float4*)(ap + 8);
            float4 v3 = *(const float4*)(ap + 12);
            float f[16] = {v0.x,v0.y,v0.z,v0.w, v1.x,v1.y,v1.z,v1.w,
                           v2.x,v2.y,v2.z,v2.w, v3.x,v3.y,v3.z,v3.w};
            float hf[16], lf[16];
#pragma unroll
            for (int j = 0; j < 16; j++) {
                __nv_bfloat16 h = __float2bfloat16(f[j]);
                hf[j] = __bfloat162float(h);
                lf[j] = f[j] - hf[j];
            }
            uint4 h0, h1, l0, l1;
            h0.x = pack_bf2(hf[0], hf[1]);  h0.y = pack_bf2(hf[2], hf[3]);
            h0.z = pack_bf2(hf[4], hf[5]);  h0.w = pack_bf2(hf[6], hf[7]);
            h1.x = pack_bf2(hf[8], hf[9]);  h1.y = pack_bf2(hf[10], hf[11]);
            h1.z = pack_bf2(hf[12], hf[13]);h1.w = pack_bf2(hf[14], hf[15]);
            l0.x = pack_bf2(lf[0], lf[1]);  l0.y = pack_bf2(lf[2], lf[3]);
            l0.z = pack_bf2(lf[4], lf[5]);  l0.w = pack_bf2(lf[6], lf[7]);
            l1.x = pack_bf2(lf[8], lf[9]);  l1.y = pack_bf2(lf[10], lf[11]);
            l1.z = pack_bf2(lf[12], lf[13]);l1.w = pack_bf2(lf[14], lf[15]);
            const int so = lr * KPAD + lh * 16;
            *(uint4*)(sAh + so)     = h0;
            *(uint4*)(sAh + so + 8) = h1;
            *(uint4*)(sAl + so)     = l0;
            *(uint4*)(sAl + so + 8) = l1;
        }
        for (int i = tid; i < PN * 4; i += 256) {
            const int row = i >> 2, q = i & 3;
            const size_t go = (size_t)row * DI + c * 32 + q * 8;
            const uint32_t so = (uint32_t)(row * KPAD + q * 8) * 2;
            cp16(bhB + so, g_Wxh + go);
            cp16(blB + so, g_Wxl + go);
        }
        CP_WAIT_ALL();
        __syncthreads();

#pragma unroll
        for (int ks = 0; ks < 2; ks++) {
            const int k0 = ks * 16;
            uint32_t ah[2][4], al[2][4];
#pragma unroll
            for (int mi = 0; mi < 2; mi++) {
                const int m0 = warpM * 32 + mi * 16;
                const uint32_t off =
                    (uint32_t)(((m0 + (lane & 15)) * KPAD + k0 + (lane >> 4) * 8) * 2);
                ldsm4(ah[mi], ahB + off);
                ldsm4(al[mi], alB + off);
            }
#pragma unroll
            for (int nj = 0; nj < 9; nj++) {
                const int n0 = warpN * 72 + nj * 8;
                const uint32_t off =
                    (uint32_t)(((n0 + (lane & 7)) * KPAD + k0 + ((lane >> 3) & 1) * 8) * 2);
                uint32_t bh[2], bl[2];
                ldsm2(bh, bhB + off);
                ldsm2(bl, blB + off);
#pragma unroll
                for (int mi = 0; mi < 2; mi++) {
                    mma16816(acc[mi][nj], ah[mi], bh);
                    mma16816(acc[mi][nj], ah[mi], bl);
                    mma16816(acc[mi][nj], al[mi], bh);
                }
            }
        }
    }

    const float Aval = -expf(*A_log);
    const int qr = lane >> 2, qc = lane & 3;
#pragma unroll
    for (int mi = 0; mi < 2; mi++) {
#pragma unroll
        for (int nj = 0; nj < 9; nj++) {
            const int m0 = rowBase + warpM * 32 + mi * 16;
            const int nn = warpN * 72 + nj * 8 + qc * 2;
            proj_store(m0 + qr,     nn,     acc[mi][nj][0], Aval);
            proj_store(m0 + qr,     nn + 1, acc[mi][nj][1], Aval);
            proj_store(m0 + qr + 8, nn,     acc[mi][nj][2], Aval);
            proj_store(m0 + qr + 8, nn + 1, acc[mi][nj][3], Aval);
        }
    }
}

// -------------------- weight transpose + bf16 hi/lo split -------------------
__device__ void wsplit_dev(const float* __restrict__ W,
                           __nv_bfloat16* __restrict__ Thi,
                           __nv_bfloat16* __restrict__ Tlo, int K, int N)
{
    __shared__ float ts[32][33];
    const int n0 = blockIdx.x * 32, k0 = blockIdx.y * 32;
    const int tx = threadIdx.x, ty = threadIdx.y;
    for (int i = ty; i < 32; i += 8)
        ts[i][tx] = W[(size_t)(k0 + i) * N + n0 + tx];
    __syncthreads();
    for (int i = ty; i < 32; i += 8) {
        float v = ts[tx][i];
        __nv_bfloat16 h = __float2bfloat16(v);
        float lf = v - __bfloat162float(h);
        size_t o = (size_t)(n0 + i) * K + k0 + tx;
        Thi[o] = h;
        Tlo[o] = __float2bfloat16(lf);
    }
}

__global__ __launch_bounds__(256)
void k_wsplit_in(const float* __restrict__ W) { wsplit_dev(W, g_Wih, g_Wil, DM, 2 * DI); }
__global__ __launch_bounds__(256)
void k_wsplit_out(const float* __restrict__ W) { wsplit_dev(W, g_Woh, g_Wol, DI, DM); }

__global__ __launch_bounds__(256)
void k_wsplit_xp(const float* __restrict__ Wxp)
{
    const int idx = blockIdx.x * 256 + threadIdx.x;
    if (idx >= PN * DI) return;
    const int n = idx / DI, k = idx % DI;
    float v = (n < 129) ? Wxp[(size_t)k * 129 + n] : 0.f;
    __nv_bfloat16 h = __float2bfloat16(v);
    g_Wxh[idx] = h;
    g_Wxl[idx] = __float2bfloat16(v - __bfloat162float(h));
}

// W_B/W_C [64, 2048] -> transposed split [2048, 64]
__global__ __launch_bounds__(256)
void k_wsplit_bc(const float* __restrict__ W_B, const float* __restrict__ W_C)
{
    const int idx = blockIdx.x * 256 + threadIdx.x;
    if (idx >= DI * DS) return;
    const int n = idx / DS, k = idx % DS;   // n in DI, k in DS
    {
        float v = W_B[(size_t)k * DI + n];
        __nv_bfloat16 h = __float2bfloat16(v);
        g_WBh[idx] = h;
        g_WBl[idx] = __float2bfloat16(v - __bfloat162float(h));
    }
    {
        float v = W_C[(size_t)k * DI + n];
        __nv_bfloat16 h = __float2bfloat16(v);
        g_WCh[idx] = h;
        g_WCl[idx] = __float2bfloat16(v - __bfloat162float(h));
    }
}

// ------------------------------- 3-phase scan ------------------------------
__global__ __launch_bounds__(256)
void scan_chunk_kernel()
{
    __shared__ float as_[CHUNK];
    const int d = blockIdx.x * blockDim.x + threadIdx.x;
    const int c = blockIdx.y, b = blockIdx.z;
    const int m0 = b * SEQ + c * CHUNK;
    if (threadIdx.x < CHUNK) as_[threadIdx.x] = g_a[m0 + threadIdx.x];
    __syncthreads();

    const float* bp = g_B  + (size_t)m0 * DI + d;
    const float* xp = g_xi + (size_t)m0 * DI + d;
    float h = 0.f;
#pragma unroll 4
    for (int t = 0; t < CHUNK; t++)
        h = fmaf(as_[t], h, bp[(size_t)t * DI] * xp[(size_t)t * DI]);

    g_Hend[((size_t)(b * NCH + c)) * DI + d] = h;
    if (blockIdx.x == 0 && threadIdx.x == 0) {
        float ap = 1.f;
#pragma unroll
        for (int t = 0; t < CHUNK; t++) ap *= as_[t];
        g_Aprod[b * NCH + c] = ap;
    }
}

__global__ __launch_bounds__(256)
void scan_carry_kernel()
{
    const int idx = blockIdx.x * blockDim.x + threadIdx.x;
    const int b = idx / DI, d = idx % DI;
    float carry = 0.f;
#pragma unroll
    for (int c = 0; c < NCH; c++) {
        size_t o = ((size_t)(b * NCH + c)) * DI + d;
        g_Hcarry[o] = carry;
        carry = fmaf(g_Aprod[b * NCH + c], carry, g_Hend[o]);
    }
}

__global__ __launch_bounds__(256)
void scan_final_kernel(const float* __restrict__ Dvec)
{
    __shared__ float as_[CHUNK];
    const int d = blockIdx.x * blockDim.x + threadIdx.x;
    const int c = blockIdx.y, b = blockIdx.z;
    const int m0 = b * SEQ + c * CHUNK;
    if (threadIdx.x < CHUNK) as_[threadIdx.x] = g_a[m0 + threadIdx.x];
    __syncthreads();

    const float* bp  = g_B  + (size_t)m0 * DI + d;
    const float* xp  = g_xi + (size_t)m0 * DI + d;
    const float* cp  = g_C  + (size_t)m0 * DI + d;
    const float* szp = g_sz + (size_t)m0 * DI + d;
    __nv_bfloat16* yhp = g_yh + (size_t)m0 * DI + d;
    __nv_bfloat16* ylp = g_yl + (size_t)m0 * DI + d;

    const float Dd = Dvec[d];
    float h = g_Hcarry[((size_t)(b * NCH + c)) * DI + d];
#pragma unroll 4
    for (int t = 0; t < CHUNK; t++) {
        float xv = xp[(size_t)t * DI];
        h = fmaf(as_[t], h, bp[(size_t)t * DI] * xv);
        float yv = fmaf(cp[(size_t)t * DI], h, Dd * xv);
        yv *= szp[(size_t)t * DI];
        __nv_bfloat16 yh = __float2bfloat16(yv);
        float yl = yv - __bfloat162float(yh);
        yhp[(size_t)t * DI] = yh;
        ylp[(size_t)t * DI] = __float2bfloat16(yl);
    }
}

// --------------------------------- launch ----------------------------------
extern "C" void kernel_launch(void* const* d_in, const int* in_sizes, int n_in,
                              void* d_out, int out_size)
{
    const float* x     = (const float*)d_in[0];
    const float* W_in  = (const float*)d_in[1];
    const float* W_xp  = (const float*)d_in[2];
    const float* W_B   = (const float*)d_in[3];
    const float* W_C   = (const float*)d_in[4];
    const float* W_out = (const float*)d_in[5];
    const float* Dvec  = (const float*)d_in[6];
    const float* A_log = (const float*)d_in[7];
    float* out = (float*)d_out;

    // 0) weight + activation splits
    k_wsplit_in <<<dim3((2 * DI) / 32, DM / 32), dim3(32, 8)>>>(W_in);
    k_wsplit_out<<<dim3(DM / 32, DI / 32),      dim3(32, 8)>>>(W_out);
    k_wsplit_xp <<<(PN * DI + 255) / 256, 256>>>(W_xp);
    k_wsplit_bc <<<(DI * DS + 255) / 256, 256>>>(W_B, W_C);
    k_split_x   <<<(MTOK * DM / 4) / 256, 256>>>(x);
    // 1) xz = x @ W_in -> xi, silu(z)
    k_mma_in<<<dim3((2 * DI) / 128, MTOK / 128), 256>>>();
    // 2) proj = xi @ W_xp -> a, Braw(hi/lo), Craw(hi/lo)
    k_proj_mma<<<MTOK / 128, 256>>>(A_log);
    // 3) B = Braw @ W_B ; C = Craw @ W_C   [mma, K=64]
    k_mma_bc<<<dim3(DI / 128, MTOK / 128, 2), 256>>>();
    // 4) chunked scan + gating -> y (split bf16)
    scan_chunk_kernel<<<dim3(DI / 256, NCH, BATCH), 256>>>();
    scan_carry_kernel<<<(BATCH * DI) / 256, 256>>>();
    scan_final_kernel<<<dim3(DI / 256, NCH, BATCH), 256>>>(Dvec);
    // 5) out = y @ W_out
    k_mma_out<<<dim3(DM / 128, MTOK / 128), 256>>>(out);
}

// round 15
// speedup vs baseline: 4.0009x; 1.0292x over previous
#include <cuda_runtime.h>
#include <cuda_bf16.h>
#include <math.h>
#include <stdint.h>

// ---------------------------------------------------------------------------
// MambaSSD — split-bf16 mma.sync GEMMs with 2-stage cp.async pipeline.
// out = ((C*h + D*xi) * silu(z)) @ W_out
// ---------------------------------------------------------------------------

#define BATCH 4
#define SEQ   2048
#define DM    1024
#define DI    2048
#define DS    64
#define MTOK  (BATCH * SEQ)   // 8192
#define NCH   16
#define CHUNK 128

// ------------------------- scratch (device globals) ------------------------
__device__ float g_xi[MTOK * DI];
__device__ float g_sz[MTOK * DI];
__device__ float g_a[MTOK];
__device__ float g_B[MTOK * DI];
__device__ float g_C[MTOK * DI];
__device__ float g_Hend[BATCH * NCH * DI];
__device__ float g_Hcarry[BATCH * NCH * DI];
__device__ float g_Aprod[BATCH * NCH];
// activations split to bf16 hi/lo
__device__ __nv_bfloat16 g_xh[MTOK * DM];
__device__ __nv_bfloat16 g_xl[MTOK * DM];
__device__ __nv_bfloat16 g_xih[MTOK * DI];       // xi split (for proj)
__device__ __nv_bfloat16 g_xil[MTOK * DI];
__device__ __nv_bfloat16 g_yh[MTOK * DI];
__device__ __nv_bfloat16 g_yl[MTOK * DI];
__device__ __nv_bfloat16 g_Brh[MTOK * DS];
__device__ __nv_bfloat16 g_Brl[MTOK * DS];
__device__ __nv_bfloat16 g_Crh[MTOK * DS];
__device__ __nv_bfloat16 g_Crl[MTOK * DS];
// transposed + split weights: [N, K] bf16 hi/lo
__device__ __nv_bfloat16 g_Wih[(2 * DI) * DM];
__device__ __nv_bfloat16 g_Wil[(2 * DI) * DM];
__device__ __nv_bfloat16 g_Woh[DM * DI];
__device__ __nv_bfloat16 g_Wol[DM * DI];
__device__ __nv_bfloat16 g_WBh[DI * DS];
__device__ __nv_bfloat16 g_WBl[DI * DS];
__device__ __nv_bfloat16 g_WCh[DI * DS];
__device__ __nv_bfloat16 g_WCl[DI * DS];
#define PN 144
__device__ __nv_bfloat16 g_Wxh[PN * DI];
__device__ __nv_bfloat16 g_Wxl[PN * DI];

// ------------------------------ PTX helpers --------------------------------
__device__ __forceinline__ uint32_t smem_u32(const void* p) {
    uint32_t a;
    asm("{ .reg .u64 t; cvta.to.shared.u64 t, %1; cvt.u32.u64 %0, t; }"
        : "=r"(a) : "l"(p));
    return a;
}

__device__ __forceinline__ void mma16816(float* d, const uint32_t* a, const uint32_t* b) {
    asm volatile(
        "mma.sync.aligned.m16n8k16.row.col.f32.bf16.bf16.f32 "
        "{%0,%1,%2,%3}, {%4,%5,%6,%7}, {%8,%9}, {%0,%1,%2,%3};"
        : "+f"(d[0]), "+f"(d[1]), "+f"(d[2]), "+f"(d[3])
        : "r"(a[0]), "r"(a[1]), "r"(a[2]), "r"(a[3]), "r"(b[0]), "r"(b[1]));
}

__device__ __forceinline__ void ldsm4(uint32_t* r, uint32_t addr) {
    asm volatile("ldmatrix.sync.aligned.m8n8.x4.shared.b16 {%0,%1,%2,%3}, [%4];"
                 : "=r"(r[0]), "=r"(r[1]), "=r"(r[2]), "=r"(r[3]) : "r"(addr));
}
__device__ __forceinline__ void ldsm2(uint32_t* r, uint32_t addr) {
    asm volatile("ldmatrix.sync.aligned.m8n8.x2.shared.b16 {%0,%1}, [%2];"
                 : "=r"(r[0]), "=r"(r[1]) : "r"(addr));
}

__device__ __forceinline__ void cp16(uint32_t saddr, const void* g) {
    asm volatile("cp.async.cg.shared.global [%0], [%1], 16;"
                 :: "r"(saddr), "l"(g) : "memory");
}
#define CP_COMMIT()   asm volatile("cp.async.commit_group;" ::: "memory")
#define CP_WAIT(n)    asm volatile("cp.async.wait_group %0;" :: "n"(n) : "memory")

__device__ __forceinline__ uint32_t pack_bf2(float a, float b) {
    __nv_bfloat162 t = __floats2bfloat162_rn(a, b);
    return *(uint32_t*)&t;
}

#define KPAD 40              // smem row stride in bf16 (80B): conflict-free ldmatrix
#define ARR_B (128 * KPAD * 2)   // bytes per smem array (10240)
#define STG_B (4 * ARR_B)        // bytes per pipeline stage (40960)
#define MMA_SMEM (2 * STG_B)     // 81920

// --------- mma.sync split-bf16 GEMM, 128x128 tile, 2-stage pipeline ---------
template<int EPI>
__device__ void mma_gemm2_dev(const __nv_bfloat16* __restrict__ Ahi,
                              const __nv_bfloat16* __restrict__ Alo,
                              const __nv_bfloat16* __restrict__ Bhi,
                              const __nv_bfloat16* __restrict__ Blo,
                              float* __restrict__ Cout, int N, int K)
{
    extern __shared__ __align__(16) char smem[];
    const uint32_t sb = smem_u32(smem);

    const int tid  = threadIdx.x;
    const int wid  = tid >> 5;
    const int lane = tid & 31;
    const int warpM = wid >> 1;
    const int warpN = wid & 1;
    const int rowBase = blockIdx.y * 128;
    const int colBase = blockIdx.x * 128;
    const int NC = K / 32;

    float acc[2][8][4];
#pragma unroll
    for (int i = 0; i < 2; i++)
#pragma unroll
        for (int j = 0; j < 8; j++)
#pragma unroll
            for (int q = 0; q < 4; q++) acc[i][j][q] = 0.f;

    // issue loads for chunk c into stage st
    auto issue = [&](int c, int st) {
        const uint32_t s0 = sb + (uint32_t)st * STG_B;
#pragma unroll
        for (int s = tid; s < 512; s += 256) {
            const int row = s >> 2, q = s & 3;
            const uint32_t so = s0 + (uint32_t)(row * KPAD + q * 8) * 2;
            const size_t ga = (size_t)(rowBase + row) * K + c * 32 + q * 8;
            const size_t gb = (size_t)(colBase + row) * K + c * 32 + q * 8;
            cp16(so,             Ahi + ga);
            cp16(so + ARR_B,     Alo + ga);
            cp16(so + 2 * ARR_B, Bhi + gb);
            cp16(so + 3 * ARR_B, Blo + gb);
        }
        CP_COMMIT();
    };

    issue(0, 0);
    for (int c = 0; c < NC; ++c) {
        if (c + 1 < NC) { issue(c + 1, (c + 1) & 1); CP_WAIT(1); }
        else            { CP_WAIT(0); }
        __syncthreads();

        const uint32_t ahB = sb + (uint32_t)(c & 1) * STG_B;
        const uint32_t alB = ahB + ARR_B;
        const uint32_t bhB = ahB + 2 * ARR_B;
        const uint32_t blB = ahB + 3 * ARR_B;

#pragma unroll
        for (int ks = 0; ks < 2; ks++) {
            const int k0 = ks * 16;
            uint32_t ah[2][4], al[2][4];
#pragma unroll
            for (int mi = 0; mi < 2; mi++) {
                const int m0 = warpM * 32 + mi * 16;
                const uint32_t off =
                    (uint32_t)(((m0 + (lane & 15)) * KPAD + k0 + (lane >> 4) * 8) * 2);
                ldsm4(ah[mi], ahB + off);
                ldsm4(al[mi], alB + off);
            }
#pragma unroll
            for (int njp = 0; njp < 4; njp++) {
                const int n0 = warpN * 64 + njp * 16;
                const uint32_t off = (uint32_t)(((n0 + (lane & 7) + ((lane >> 4) & 1) * 8)
                                     * KPAD + k0 + ((lane >> 3) & 1) * 8) * 2);
                uint32_t bh[4], bl[4];
                ldsm4(bh, bhB + off);
                ldsm4(bl, blB + off);
#pragma unroll
                for (int mi = 0; mi < 2; mi++) {
                    mma16816(acc[mi][njp * 2],     ah[mi], bh);
                    mma16816(acc[mi][njp * 2],     ah[mi], bl);
                    mma16816(acc[mi][njp * 2],     al[mi], bh);
                    mma16816(acc[mi][njp * 2 + 1], ah[mi], bh + 2);
                    mma16816(acc[mi][njp * 2 + 1], ah[mi], bl + 2);
                    mma16816(acc[mi][njp * 2 + 1], al[mi], bh + 2);
                }
            }
        }
        __syncthreads();
    }

    const int qr = lane >> 2, qc = lane & 3;
#pragma unroll
    for (int mi = 0; mi < 2; mi++) {
#pragma unroll
        for (int nj = 0; nj < 8; nj++) {
            const int m0 = rowBase + warpM * 32 + mi * 16;
            const int nn = warpN * 64 + nj * 8 + qc * 2;
            float c0 = acc[mi][nj][0], c1 = acc[mi][nj][1];
            float c2 = acc[mi][nj][2], c3 = acc[mi][nj][3];
            if (EPI == 0) {
                float* p0 = Cout + (size_t)(m0 + qr) * N + colBase + nn;
                float* p1 = Cout + (size_t)(m0 + qr + 8) * N + colBase + nn;
                *(float2*)p0 = make_float2(c0, c1);
                *(float2*)p1 = make_float2(c2, c3);
            } else {
                const bool zside = (colBase >= DI);
                const int cb = (zside ? colBase - DI : colBase) + nn;
                if (zside) {
                    c0 = c0 / (1.f + expf(-c0));
                    c1 = c1 / (1.f + expf(-c1));
                    c2 = c2 / (1.f + expf(-c2));
                    c3 = c3 / (1.f + expf(-c3));
                    *(float2*)(g_sz + (size_t)(m0 + qr) * DI + cb)     = make_float2(c0, c1);
                    *(float2*)(g_sz + (size_t)(m0 + qr + 8) * DI + cb) = make_float2(c2, c3);
                } else {
                    *(float2*)(g_xi + (size_t)(m0 + qr) * DI + cb)     = make_float2(c0, c1);
                    *(float2*)(g_xi + (size_t)(m0 + qr + 8) * DI + cb) = make_float2(c2, c3);
                    // bf16 hi/lo split for proj
                    __nv_bfloat16 h0 = __float2bfloat16(c0), h1 = __float2bfloat16(c1);
                    __nv_bfloat16 h2 = __float2bfloat16(c2), h3 = __float2bfloat16(c3);
                    *(uint32_t*)(g_xih + (size_t)(m0 + qr) * DI + cb) =
                        pack_bf2(__bfloat162float(h0), __bfloat162float(h1));
                    *(uint32_t*)(g_xih + (size_t)(m0 + qr + 8) * DI + cb) =
                        pack_bf2(__bfloat162float(h2), __bfloat162float(h3));
                    *(uint32_t*)(g_xil + (size_t)(m0 + qr) * DI + cb) =
                        pack_bf2(c0 - __bfloat162float(h0), c1 - __bfloat162float(h1));
                    *(uint32_t*)(g_xil + (size_t)(m0 + qr + 8) * DI + cb) =
                        pack_bf2(c2 - __bfloat162float(h2), c3 - __bfloat162float(h3));
                }
            }
        }
    }
}

__global__ __launch_bounds__(256, 2)
void k_mma_in()
{
    mma_gemm2_dev<1>(g_xh, g_xl, g_Wih, g_Wil, nullptr, 2 * DI, DM);
}

__global__ __launch_bounds__(256, 2)
void k_mma_out(float* __restrict__ out)
{
    mma_gemm2_dev<0>(g_yh, g_yl, g_Woh, g_Wol, out, DM, DI);
}

__global__ __launch_bounds__(256, 2)
void k_mma_bc()
{
    if (blockIdx.z == 0)
        mma_gemm2_dev<0>(g_Brh, g_Brl, g_WBh, g_WBl, g_B, DI, DS);
    else
        mma_gemm2_dev<0>(g_Crh, g_Crl, g_WCh, g_WCl, g_C, DI, DS);
}

// -------------------- activation split: x -> g_xh/g_xl ---------------------
__global__ __launch_bounds__(256)
void k_split_x(const float* __restrict__ x)
{
    const int idx4 = blockIdx.x * 256 + threadIdx.x;
    const size_t base = (size_t)idx4 * 4;
    float4 v = *(const float4*)(x + base);
    float f[4] = {v.x, v.y, v.z, v.w};
    float lf[4];
    __nv_bfloat16 h[4];
#pragma unroll
    for (int j = 0; j < 4; j++) {
        h[j] = __float2bfloat16(f[j]);
        lf[j] = f[j] - __bfloat162float(h[j]);
    }
    *(uint2*)(g_xh + base) = make_uint2(
        pack_bf2(__bfloat162float(h[0]), __bfloat162float(h[1])),
        pack_bf2(__bfloat162float(h[2]), __bfloat162float(h[3])));
    *(uint2*)(g_xl + base) = make_uint2(pack_bf2(lf[0], lf[1]), pack_bf2(lf[2], lf[3]));
}

// ----------------- proj = xi @ W_xp via mma.sync (N pad 144) ----------------
__device__ __forceinline__ void proj_store(int m, int col, float v, float Aval)
{
    if (col == 0) {
        float dlt = (v > 20.f) ? v : log1pf(expf(v));
        g_a[m] = expf(Aval * dlt);
    } else if (col <= 2 * DS) {
        __nv_bfloat16 h = __float2bfloat16(v);
        __nv_bfloat16 l = __float2bfloat16(v - __bfloat162float(h));
        if (col <= DS) {
            g_Brh[(size_t)m * DS + (col - 1)] = h;
            g_Brl[(size_t)m * DS + (col - 1)] = l;
        } else {
            g_Crh[(size_t)m * DS + (col - 1 - DS)] = h;
            g_Crl[(size_t)m * DS + (col - 1 - DS)] = l;
        }
    }
}

__global__ __launch_bounds__(256, 1)
void k_proj_mma(const float* __restrict__ A_log)
{
    __shared__ __align__(16) __nv_bfloat16 sAh[128 * KPAD];
    __shared__ __align__(16) __nv_bfloat16 sAl[128 * KPAD];
    __shared__ __align__(16) __nv_bfloat16 sBh[PN * KPAD];
    __shared__ __align__(16) __nv_bfloat16 sBl[PN * KPAD];

    const int tid  = threadIdx.x;
    const int wid  = tid >> 5;
    const int lane = tid & 31;
    const int warpM = wid >> 1;
    const int warpN = wid & 1;
    const int rowBase = blockIdx.x * 128;
    const int NC = DI / 32;

    const uint32_t ahB = smem_u32(sAh);
    const uint32_t alB = smem_u32(sAl);
    const uint32_t bhB = smem_u32(sBh);
    const uint32_t blB = smem_u32(sBl);

    float acc[2][9][4];
#pragma unroll
    for (int i = 0; i < 2; i++)
#pragma unroll
        for (int j = 0; j < 9; j++)
#pragma unroll
            for (int q = 0; q < 4; q++) acc[i][j][q] = 0.f;

    for (int c = 0; c < NC; ++c) {
        __syncthreads();
#pragma unroll
        for (int s = tid; s < 512; s += 256) {
            const int row = s >> 2, q = s & 3;
            const uint32_t so = (uint32_t)(row * KPAD + q * 8) * 2;
            const size_t ga = (size_t)(rowBase + row) * DI + c * 32 + q * 8;
            cp16(ahB + so, g_xih + ga);
            cp16(alB + so, g_xil + ga);
        }
        for (int i = tid; i < PN * 4; i += 256) {
            const int row = i >> 2, q = i & 3;
            const size_t go = (size_t)row * DI + c * 32 + q * 8;
            const uint32_t so = (uint32_t)(row * KPAD + q * 8) * 2;
            cp16(bhB + so, g_Wxh + go);
            cp16(blB + so, g_Wxl + go);
        }
        CP_COMMIT();
        CP_WAIT(0);
        __syncthreads();

#pragma unroll
        for (int ks = 0; ks < 2; ks++) {
            const int k0 = ks * 16;
            uint32_t ah[2][4], al[2][4];
#pragma unroll
            for (int mi = 0; mi < 2; mi++) {
                const int m0 = warpM * 32 + mi * 16;
                const uint32_t off =
                    (uint32_t)(((m0 + (lane & 15)) * KPAD + k0 + (lane >> 4) * 8) * 2);
                ldsm4(ah[mi], ahB + off);
                ldsm4(al[mi], alB + off);
            }
#pragma unroll
            for (int nj = 0; nj < 9; nj++) {
                const int n0 = warpN * 72 + nj * 8;
                const uint32_t off =
                    (uint32_t)(((n0 + (lane & 7)) * KPAD + k0 + ((lane >> 3) & 1) * 8) * 2);
                uint32_t bh[2], bl[2];
                ldsm2(bh, bhB + off);
                ldsm2(bl, blB + off);
#pragma unroll
                for (int mi = 0; mi < 2; mi++) {
                    mma16816(acc[mi][nj], ah[mi], bh);
                    mma16816(acc[mi][nj], ah[mi], bl);
                    mma16816(acc[mi][nj], al[mi], bh);
                }
            }
        }
    }

    const float Aval = -expf(*A_log);
    const int qr = lane >> 2, qc = lane & 3;
#pragma unroll
    for (int mi = 0; mi < 2; mi++) {
#pragma unroll
        for (int nj = 0; nj < 9; nj++) {
            const int m0 = rowBase + warpM * 32 + mi * 16;
            const int nn = warpN * 72 + nj * 8 + qc * 2;
            proj_store(m0 + qr,     nn,     acc[mi][nj][0], Aval);
            proj_store(m0 + qr,     nn + 1, acc[mi][nj][1], Aval);
            proj_store(m0 + qr + 8, nn,     acc[mi][nj][2], Aval);
            proj_store(m0 + qr + 8, nn + 1, acc[mi][nj][3], Aval);
        }
    }
}

// -------------------- weight transpose + bf16 hi/lo split -------------------
__device__ void wsplit_dev(const float* __restrict__ W,
                           __nv_bfloat16* __restrict__ Thi,
                           __nv_bfloat16* __restrict__ Tlo, int K, int N)
{
    __shared__ float ts[32][33];
    const int n0 = blockIdx.x * 32, k0 = blockIdx.y * 32;
    const int tx = threadIdx.x, ty = threadIdx.y;
    for (int i = ty; i < 32; i += 8)
        ts[i][tx] = W[(size_t)(k0 + i) * N + n0 + tx];
    __syncthreads();
    for (int i = ty; i < 32; i += 8) {
        float v = ts[tx][i];
        __nv_bfloat16 h = __float2bfloat16(v);
        float lf = v - __bfloat162float(h);
        size_t o = (size_t)(n0 + i) * K + k0 + tx;
        Thi[o] = h;
        Tlo[o] = __float2bfloat16(lf);
    }
}

__global__ __launch_bounds__(256)
void k_wsplit_in(const float* __restrict__ W) { wsplit_dev(W, g_Wih, g_Wil, DM, 2 * DI); }
__global__ __launch_bounds__(256)
void k_wsplit_out(const float* __restrict__ W) { wsplit_dev(W, g_Woh, g_Wol, DI, DM); }

__global__ __launch_bounds__(256)
void k_wsplit_xp(const float* __restrict__ Wxp)
{
    const int idx = blockIdx.x * 256 + threadIdx.x;
    if (idx >= PN * DI) return;
    const int n = idx / DI, k = idx % DI;
    float v = (n < 129) ? Wxp[(size_t)k * 129 + n] : 0.f;
    __nv_bfloat16 h = __float2bfloat16(v);
    g_Wxh[idx] = h;
    g_Wxl[idx] = __float2bfloat16(v - __bfloat162float(h));
}

__global__ __launch_bounds__(256)
void k_wsplit_bc(const float* __restrict__ W_B, const float* __restrict__ W_C)
{
    const int idx = blockIdx.x * 256 + threadIdx.x;
    if (idx >= DI * DS) return;
    const int n = idx / DS, k = idx % DS;
    {
        float v = W_B[(size_t)k * DI + n];
        __nv_bfloat16 h = __float2bfloat16(v);
        g_WBh[idx] = h;
        g_WBl[idx] = __float2bfloat16(v - __bfloat162float(h));
    }
    {
        float v = W_C[(size_t)k * DI + n];
        __nv_bfloat16 h = __float2bfloat16(v);
        g_WCh[idx] = h;
        g_WCl[idx] = __float2bfloat16(v - __bfloat162float(h));
    }
}

// ------------------------------- 3-phase scan ------------------------------
__global__ __launch_bounds__(256)
void scan_chunk_kernel()
{
    __shared__ float as_[CHUNK];
    const int d = blockIdx.x * blockDim.x + threadIdx.x;
    const int c = blockIdx.y, b = blockIdx.z;
    const int m0 = b * SEQ + c * CHUNK;
    if (threadIdx.x < CHUNK) as_[threadIdx.x] = g_a[m0 + threadIdx.x];
    __syncthreads();

    const float* bp = g_B  + (size_t)m0 * DI + d;
    const float* xp = g_xi + (size_t)m0 * DI + d;
    float h = 0.f;
#pragma unroll 4
    for (int t = 0; t < CHUNK; t++)
        h = fmaf(as_[t], h, bp[(size_t)t * DI] * xp[(size_t)t * DI]);

    g_Hend[((size_t)(b * NCH + c)) * DI + d] = h;
    if (blockIdx.x == 0 && threadIdx.x == 0) {
        float ap = 1.f;
#pragma unroll
        for (int t = 0; t < CHUNK; t++) ap *= as_[t];
        g_Aprod[b * NCH + c] = ap;
    }
}

__global__ __launch_bounds__(256)
void scan_carry_kernel()
{
    const int idx = blockIdx.x * blockDim.x + threadIdx.x;
    const int b = idx / DI, d = idx % DI;
    float carry = 0.f;
#pragma unroll
    for (int c = 0; c < NCH; c++) {
        size_t o = ((size_t)(b * NCH + c)) * DI + d;
        g_Hcarry[o] = carry;
        carry = fmaf(g_Aprod[b * NCH + c], carry, g_Hend[o]);
    }
}

__global__ __launch_bounds__(256)
void scan_final_kernel(const float* __restrict__ Dvec)
{
    __shared__ float as_[CHUNK];
    const int d = blockIdx.x * blockDim.x + threadIdx.x;
    const int c = blockIdx.y, b = blockIdx.z;
    const int m0 = b * SEQ + c * CHUNK;
    if (threadIdx.x < CHUNK) as_[threadIdx.x] = g_a[m0 + threadIdx.x];
    __syncthreads();

    const float* bp  = g_B  + (size_t)m0 * DI + d;
    const float* xp  = g_xi + (size_t)m0 * DI + d;
    const float* cp  = g_C  + (size_t)m0 * DI + d;
    const float* szp = g_sz + (size_t)m0 * DI + d;
    __nv_bfloat16* yhp = g_yh + (size_t)m0 * DI + d;
    __nv_bfloat16* ylp = g_yl + (size_t)m0 * DI + d;

    const float Dd = Dvec[d];
    float h = g_Hcarry[((size_t)(b * NCH + c)) * DI + d];
#pragma unroll 4
    for (int t = 0; t < CHUNK; t++) {
        float xv = xp[(size_t)t * DI];
        h = fmaf(as_[t], h, bp[(size_t)t * DI] * xv);
        float yv = fmaf(cp[(size_t)t * DI], h, Dd * xv);
        yv *= szp[(size_t)t * DI];
        __nv_bfloat16 yh = __float2bfloat16(yv);
        float yl = yv - __bfloat162float(yh);
        yhp[(size_t)t * DI] = yh;
        ylp[(size_t)t * DI] = __float2bfloat16(yl);
    }
}

// --------------------------------- launch ----------------------------------
extern "C" void kernel_launch(void* const* d_in, const int* in_sizes, int n_in,
                              void* d_out, int out_size)
{
    const float* x     = (const float*)d_in[0];
    const float* W_in  = (const float*)d_in[1];
    const float* W_xp  = (const float*)d_in[2];
    const float* W_B   = (const float*)d_in[3];
    const float* W_C   = (const float*)d_in[4];
    const float* W_out = (const float*)d_in[5];
    const float* Dvec  = (const float*)d_in[6];
    const float* A_log = (const float*)d_in[7];
    float* out = (float*)d_out;

    cudaFuncSetAttribute(k_mma_in,  cudaFuncAttributeMaxDynamicSharedMemorySize, MMA_SMEM);
    cudaFuncSetAttribute(k_mma_out, cudaFuncAttributeMaxDynamicSharedMemorySize, MMA_SMEM);
    cudaFuncSetAttribute(k_mma_bc,  cudaFuncAttributeMaxDynamicSharedMemorySize, MMA_SMEM);

    // 0) weight + activation splits
    k_wsplit_in <<<dim3((2 * DI) / 32, DM / 32), dim3(32, 8)>>>(W_in);
    k_wsplit_out<<<dim3(DM / 32, DI / 32),      dim3(32, 8)>>>(W_out);
    k_wsplit_xp <<<(PN * DI + 255) / 256, 256>>>(W_xp);
    k_wsplit_bc <<<(DI * DS + 255) / 256, 256>>>(W_B, W_C);
    k_split_x   <<<(MTOK * DM / 4) / 256, 256>>>(x);
    // 1) xz = x @ W_in -> xi (fp32 + bf16 split), silu(z)
    k_mma_in<<<dim3((2 * DI) / 128, MTOK / 128), 256, MMA_SMEM>>>();
    // 2) proj = xi @ W_xp -> a, Braw(hi/lo), Craw(hi/lo)
    k_proj_mma<<<MTOK / 128, 256>>>(A_log);
    // 3) B = Braw @ W_B ; C = Craw @ W_C
    k_mma_bc<<<dim3(DI / 128, MTOK / 128, 2), 256, MMA_SMEM>>>();
    // 4) chunked scan + gating -> y (split bf16)
    scan_chunk_kernel<<<dim3(DI / 256, NCH, BATCH), 256>>>();
    scan_carry_kernel<<<(BATCH * DI) / 256, 256>>>();
    scan_final_kernel<<<dim3(DI / 256, NCH, BATCH), 256>>>(Dvec);
    // 5) out = y @ W_out
    k_mma_out<<<dim3(DM / 128, MTOK / 128), 256, MMA_SMEM>>>(out);
}